// round 2
// baseline (speedup 1.0000x reference)
#include <cuda_runtime.h>
#include <cuda_bf16.h>

#define EN   1024
#define DFFN 4096
#define NB   2
#define LL   2048
#define HHH  16
#define DDD  64
#define ROWS (NB*LL)   // 4096

// ---------------- scratch (device globals; no allocation allowed) ----------
__device__ float g_h   [ROWS*EN];      // LN1 output
__device__ float g_qkv [ROWS*3*EN];    // QKV projection
__device__ float g_attn[ROWS*EN];      // attention output (pre-Wo)
__device__ float g_x1  [ROWS*EN];      // x + attn@Wo + bo
__device__ float g_h2  [ROWS*EN];      // LN2(LNf(...)) output
__device__ float g_ff  [ROWS*DFFN];    // gelu(h2@W1+b1)

// ---------------- helpers ---------------------------------------------------
__device__ __forceinline__ unsigned f2tf32(float f) {
    unsigned r;
    asm("cvt.rna.tf32.f32 %0, %1;" : "=r"(r) : "f"(f));
    return r;
}

__device__ __forceinline__ void mma_tf32(float* c, const unsigned* a, unsigned b0, unsigned b1) {
    asm volatile(
        "mma.sync.aligned.m16n8k8.row.col.f32.tf32.tf32.f32 "
        "{%0,%1,%2,%3},{%4,%5,%6,%7},{%8,%9},{%0,%1,%2,%3};"
        : "+f"(c[0]), "+f"(c[1]), "+f"(c[2]), "+f"(c[3])
        : "r"(a[0]), "r"(a[1]), "r"(a[2]), "r"(a[3]), "r"(b0), "r"(b1));
}

__device__ __forceinline__ void mma_bf16(float* c, const unsigned* a, unsigned b0, unsigned b1) {
    asm volatile(
        "mma.sync.aligned.m16n8k16.row.col.f32.bf16.bf16.f32 "
        "{%0,%1,%2,%3},{%4,%5,%6,%7},{%8,%9},{%0,%1,%2,%3};"
        : "+f"(c[0]), "+f"(c[1]), "+f"(c[2]), "+f"(c[3])
        : "r"(a[0]), "r"(a[1]), "r"(a[2]), "r"(a[3]), "r"(b0), "r"(b1));
}

__device__ __forceinline__ unsigned pack_bf16(float lo, float hi) {
    __nv_bfloat162 p = __floats2bfloat162_rn(lo, hi);  // .x = lo (low 16), .y = hi
    return *reinterpret_cast<unsigned*>(&p);
}

// block = 256 threads (8 warps). Reduces (a,b) across the block.
__device__ __forceinline__ void blockReduce2(float& a, float& b) {
    __shared__ float sm[16];
    #pragma unroll
    for (int o = 16; o; o >>= 1) {
        a += __shfl_xor_sync(0xFFFFFFFFu, a, o);
        b += __shfl_xor_sync(0xFFFFFFFFu, b, o);
    }
    int w = threadIdx.x >> 5, lane = threadIdx.x & 31;
    __syncthreads();                       // protect sm from previous use
    if (lane == 0) { sm[w] = a; sm[8 + w] = b; }
    __syncthreads();
    a = 0.f; b = 0.f;
    #pragma unroll
    for (int i = 0; i < 8; i++) { a += sm[i]; b += sm[8 + i]; }
}

// ---------------- LN1: h = LN(x)*s + b  (4096 rows, 1 f4/thread) ------------
__global__ __launch_bounds__(256) void ln1_k(const float* __restrict__ x,
                                             const float* __restrict__ s,
                                             const float* __restrict__ b,
                                             float* __restrict__ out) {
    int row = blockIdx.x, t = threadIdx.x;
    float4 v = reinterpret_cast<const float4*>(x + (size_t)row * EN)[t];
    float sum = v.x + v.y + v.z + v.w;
    float sq  = v.x*v.x + v.y*v.y + v.z*v.z + v.w*v.w;
    blockReduce2(sum, sq);
    float mu = sum * (1.f / EN);
    float rs = rsqrtf(sq * (1.f / EN) - mu * mu + 1e-5f);
    float4 sv = reinterpret_cast<const float4*>(s)[t];
    float4 bv = reinterpret_cast<const float4*>(b)[t];
    float4 o;
    o.x = (v.x - mu) * rs * sv.x + bv.x;
    o.y = (v.y - mu) * rs * sv.y + bv.y;
    o.z = (v.z - mu) * rs * sv.z + bv.z;
    o.w = (v.w - mu) * rs * sv.w + bv.w;
    reinterpret_cast<float4*>(out + (size_t)row * EN)[t] = o;
}

// ---------------- LN2 then LNf fused ----------------------------------------
__global__ __launch_bounds__(256) void ln2f_k(const float* __restrict__ x,
                                              const float* __restrict__ s2,
                                              const float* __restrict__ b2,
                                              const float* __restrict__ sf,
                                              const float* __restrict__ bf,
                                              float* __restrict__ out) {
    int row = blockIdx.x, t = threadIdx.x;
    float4 v = reinterpret_cast<const float4*>(x + (size_t)row * EN)[t];
    float sum = v.x + v.y + v.z + v.w;
    float sq  = v.x*v.x + v.y*v.y + v.z*v.z + v.w*v.w;
    blockReduce2(sum, sq);
    float mu = sum * (1.f / EN);
    float rs = rsqrtf(sq * (1.f / EN) - mu * mu + 1e-5f);
    float4 sv = reinterpret_cast<const float4*>(s2)[t];
    float4 bv = reinterpret_cast<const float4*>(b2)[t];
    float4 y;
    y.x = (v.x - mu) * rs * sv.x + bv.x;
    y.y = (v.y - mu) * rs * sv.y + bv.y;
    y.z = (v.z - mu) * rs * sv.z + bv.z;
    y.w = (v.w - mu) * rs * sv.w + bv.w;
    float sum2 = y.x + y.y + y.z + y.w;
    float sq2  = y.x*y.x + y.y*y.y + y.z*y.z + y.w*y.w;
    blockReduce2(sum2, sq2);
    float mu2 = sum2 * (1.f / EN);
    float rs2 = rsqrtf(sq2 * (1.f / EN) - mu2 * mu2 + 1e-5f);
    float4 fv = reinterpret_cast<const float4*>(sf)[t];
    float4 gv = reinterpret_cast<const float4*>(bf)[t];
    float4 o;
    o.x = (y.x - mu2) * rs2 * fv.x + gv.x;
    o.y = (y.y - mu2) * rs2 * fv.y + gv.y;
    o.z = (y.z - mu2) * rs2 * fv.z + gv.z;
    o.w = (y.w - mu2) * rs2 * fv.w + gv.w;
    reinterpret_cast<float4*>(out + (size_t)row * EN)[t] = o;
}

// ---------------- tf32 GEMM: C = epi(A@B + bias [+ res]) --------------------
// A [M,K] row-major fp32, B [K,N] row-major fp32. BM=BN=128, BK=32, 256 thr.
#define EPI_BIAS 0
#define EPI_GELU 1
#define EPI_RES  2

template <int EPI>
__global__ __launch_bounds__(256) void gemm_k(int M, int N, int K,
                                              const float* __restrict__ A,
                                              const float* __restrict__ B,
                                              const float* __restrict__ bias,
                                              const float* __restrict__ res,
                                              float* __restrict__ C) {
    __shared__ float sA[128][36];   // bank = 4g+tg (conflict-free frag loads)
    __shared__ float sB[32][136];   // bank = 8tg+g
    int bm = blockIdx.y * 128, bn = blockIdx.x * 128;
    int t = threadIdx.x, wid = t >> 5, lane = t & 31;
    int g = lane >> 2, tg = lane & 3;
    int wr = (wid & 3) * 32;        // warp row base (32 rows)
    int wc = (wid >> 2) * 64;       // warp col base (64 cols)

    float c[2][8][4];
    #pragma unroll
    for (int mi = 0; mi < 2; mi++)
        #pragma unroll
        for (int nj = 0; nj < 8; nj++)
            #pragma unroll
            for (int q = 0; q < 4; q++) c[mi][nj][q] = 0.f;

    for (int k0 = 0; k0 < K; k0 += 32) {
        #pragma unroll
        for (int i = 0; i < 4; i++) {
            int id = t + i * 256;
            int row = id >> 3, c4 = (id & 7) * 4;
            float4 v = *reinterpret_cast<const float4*>(A + (size_t)(bm + row) * K + k0 + c4);
            sA[row][c4 + 0] = __uint_as_float(f2tf32(v.x));
            sA[row][c4 + 1] = __uint_as_float(f2tf32(v.y));
            sA[row][c4 + 2] = __uint_as_float(f2tf32(v.z));
            sA[row][c4 + 3] = __uint_as_float(f2tf32(v.w));
        }
        #pragma unroll
        for (int i = 0; i < 4; i++) {
            int id = t + i * 256;
            int row = id >> 5, c4 = (id & 31) * 4;
            float4 v = *reinterpret_cast<const float4*>(B + (size_t)(k0 + row) * N + bn + c4);
            sB[row][c4 + 0] = __uint_as_float(f2tf32(v.x));
            sB[row][c4 + 1] = __uint_as_float(f2tf32(v.y));
            sB[row][c4 + 2] = __uint_as_float(f2tf32(v.z));
            sB[row][c4 + 3] = __uint_as_float(f2tf32(v.w));
        }
        __syncthreads();
        #pragma unroll
        for (int kk = 0; kk < 32; kk += 8) {
            unsigned a[2][4], bf2[8][2];
            #pragma unroll
            for (int mi = 0; mi < 2; mi++) {
                a[mi][0] = __float_as_uint(sA[wr + mi*16 + g    ][kk + tg    ]);
                a[mi][1] = __float_as_uint(sA[wr + mi*16 + g + 8][kk + tg    ]);
                a[mi][2] = __float_as_uint(sA[wr + mi*16 + g    ][kk + tg + 4]);
                a[mi][3] = __float_as_uint(sA[wr + mi*16 + g + 8][kk + tg + 4]);
            }
            #pragma unroll
            for (int nj = 0; nj < 8; nj++) {
                bf2[nj][0] = __float_as_uint(sB[kk + tg    ][wc + nj*8 + g]);
                bf2[nj][1] = __float_as_uint(sB[kk + tg + 4][wc + nj*8 + g]);
            }
            #pragma unroll
            for (int mi = 0; mi < 2; mi++)
                #pragma unroll
                for (int nj = 0; nj < 8; nj++)
                    mma_tf32(c[mi][nj], a[mi], bf2[nj][0], bf2[nj][1]);
        }
        __syncthreads();
    }

    #pragma unroll
    for (int mi = 0; mi < 2; mi++) {
        #pragma unroll
        for (int nj = 0; nj < 8; nj++) {
            int row = bm + wr + mi * 16 + g;
            int col = bn + wc + nj * 8 + tg * 2;
            float b0 = bias[col], b1 = bias[col + 1];
            float v0 = c[mi][nj][0] + b0, v1 = c[mi][nj][1] + b1;
            float v2 = c[mi][nj][2] + b0, v3 = c[mi][nj][3] + b1;
            if (EPI == EPI_GELU) {
                v0 = 0.5f * v0 * (1.f + erff(v0 * 0.70710678118f));
                v1 = 0.5f * v1 * (1.f + erff(v1 * 0.70710678118f));
                v2 = 0.5f * v2 * (1.f + erff(v2 * 0.70710678118f));
                v3 = 0.5f * v3 * (1.f + erff(v3 * 0.70710678118f));
            }
            if (EPI == EPI_RES) {
                float2 r0 = *reinterpret_cast<const float2*>(res + (size_t)row * N + col);
                float2 r1 = *reinterpret_cast<const float2*>(res + (size_t)(row + 8) * N + col);
                v0 += r0.x; v1 += r0.y; v2 += r1.x; v3 += r1.y;
            }
            *reinterpret_cast<float2*>(C + (size_t)row * N + col)       = make_float2(v0, v1);
            *reinterpret_cast<float2*>(C + (size_t)(row + 8) * N + col) = make_float2(v2, v3);
        }
    }
}

// ---------------- bf16 flash attention --------------------------------------
// grid (L/64 q-tiles, N*H); block 128 (4 warps, 16 q-rows/warp). KV tile 128.
// Mask is a 32-bit-per-element tensor (bool coerced by harness to int32 or
// float32); "masked" <=> word != 0 (covers both encodings).
#define NEG_BIG (-60000.0f)

__global__ __launch_bounds__(128) void attn_k(const unsigned* __restrict__ mask) {
    __shared__ __nv_bfloat16 sQ [64][72];    // [q][d], stride 72 -> bank=lane
    __shared__ __nv_bfloat16 sK [128][72];   // [kv][d]
    __shared__ __nv_bfloat16 sVt[64][136];   // [d][kv], transposed

    int t = threadIdx.x, w = t >> 5, lane = t & 31;
    int g = lane >> 2, tg = lane & 3;
    int qt = blockIdx.x, nh = blockIdx.y;
    int n = nh >> 4, h = nh & 15;
    size_t qrow0 = (size_t)n * LL + (size_t)qt * 64;

    // load Q (scaled by 1/sqrt(D)=0.125), 8 f4 per thread
    #pragma unroll
    for (int i = 0; i < 8; i++) {
        int id = t + i * 128;
        int r = id >> 4, c4 = (id & 15) * 4;
        float4 v = *reinterpret_cast<const float4*>(g_qkv + (qrow0 + r) * 3072 + h * 64 + c4);
        sQ[r][c4 + 0] = __float2bfloat16(v.x * 0.125f);
        sQ[r][c4 + 1] = __float2bfloat16(v.y * 0.125f);
        sQ[r][c4 + 2] = __float2bfloat16(v.z * 0.125f);
        sQ[r][c4 + 3] = __float2bfloat16(v.w * 0.125f);
    }
    __syncthreads();

    // hoist Q fragments (invariant over kv loop)
    unsigned aQ[4][4];
    #pragma unroll
    for (int tt = 0; tt < 4; tt++) {
        aQ[tt][0] = *reinterpret_cast<unsigned*>(&sQ[w*16 + g    ][tt*16 + 2*tg    ]);
        aQ[tt][1] = *reinterpret_cast<unsigned*>(&sQ[w*16 + g + 8][tt*16 + 2*tg    ]);
        aQ[tt][2] = *reinterpret_cast<unsigned*>(&sQ[w*16 + g    ][tt*16 + 2*tg + 8]);
        aQ[tt][3] = *reinterpret_cast<unsigned*>(&sQ[w*16 + g + 8][tt*16 + 2*tg + 8]);
    }

    float O[8][4];
    #pragma unroll
    for (int nj = 0; nj < 8; nj++)
        #pragma unroll
        for (int q = 0; q < 4; q++) O[nj][q] = 0.f;
    float m0 = NEG_BIG, m1 = NEG_BIG, l0 = 0.f, l1 = 0.f;

    size_t mrow = (size_t)nh * LL + (size_t)qt * 64 + w * 16;

    for (int kv0 = 0; kv0 < LL; kv0 += 128) {
        __syncthreads();   // previous tile consumed
        #pragma unroll
        for (int i = 0; i < 16; i++) {
            int id = t + i * 128;
            int r = id >> 4, c4 = (id & 15) * 4;
            size_t base = ((size_t)n * LL + kv0 + r) * 3072 + h * 64 + c4;
            float4 kv = *reinterpret_cast<const float4*>(g_qkv + base + 1024);
            sK[r][c4 + 0] = __float2bfloat16(kv.x);
            sK[r][c4 + 1] = __float2bfloat16(kv.y);
            sK[r][c4 + 2] = __float2bfloat16(kv.z);
            sK[r][c4 + 3] = __float2bfloat16(kv.w);
            float4 vv = *reinterpret_cast<const float4*>(g_qkv + base + 2048);
            sVt[c4 + 0][r] = __float2bfloat16(vv.x);
            sVt[c4 + 1][r] = __float2bfloat16(vv.y);
            sVt[c4 + 2][r] = __float2bfloat16(vv.z);
            sVt[c4 + 3][r] = __float2bfloat16(vv.w);
        }
        __syncthreads();

        // S = Q K^T  (16 rows x 128 cols per warp)
        float s[16][4];
        #pragma unroll
        for (int j = 0; j < 16; j++) {
            s[j][0] = s[j][1] = s[j][2] = s[j][3] = 0.f;
            #pragma unroll
            for (int tt = 0; tt < 4; tt++) {
                unsigned b0 = *reinterpret_cast<unsigned*>(&sK[j*8 + g][tt*16 + 2*tg    ]);
                unsigned b1 = *reinterpret_cast<unsigned*>(&sK[j*8 + g][tt*16 + 2*tg + 8]);
                mma_bf16(s[j], aQ[tt], b0, b1);
            }
        }

        // mask (32-bit words; nonzero -> -inf). Rows mrow+g and mrow+g+8,
        // cols kv0 + j*8 + 2tg (+1): one uint2 per row per j.
        const unsigned* mr0 = mask + (mrow + g)     * (size_t)LL + kv0;
        const unsigned* mr1 = mask + (mrow + g + 8) * (size_t)LL + kv0;
        #pragma unroll
        for (int j = 0; j < 16; j++) {
            int col = j * 8 + 2 * tg;
            uint2 p0 = *reinterpret_cast<const uint2*>(mr0 + col);
            uint2 p1 = *reinterpret_cast<const uint2*>(mr1 + col);
            if (p0.x) s[j][0] = NEG_BIG;
            if (p0.y) s[j][1] = NEG_BIG;
            if (p1.x) s[j][2] = NEG_BIG;
            if (p1.y) s[j][3] = NEG_BIG;
        }

        // online softmax
        float tm0 = NEG_BIG, tm1 = NEG_BIG;
        #pragma unroll
        for (int j = 0; j < 16; j++) {
            tm0 = fmaxf(tm0, fmaxf(s[j][0], s[j][1]));
            tm1 = fmaxf(tm1, fmaxf(s[j][2], s[j][3]));
        }
        tm0 = fmaxf(tm0, __shfl_xor_sync(0xFFFFFFFFu, tm0, 1));
        tm0 = fmaxf(tm0, __shfl_xor_sync(0xFFFFFFFFu, tm0, 2));
        tm1 = fmaxf(tm1, __shfl_xor_sync(0xFFFFFFFFu, tm1, 1));
        tm1 = fmaxf(tm1, __shfl_xor_sync(0xFFFFFFFFu, tm1, 2));
        float nm0 = fmaxf(m0, tm0), nm1 = fmaxf(m1, tm1);
        float f0 = __expf(m0 - nm0), f1 = __expf(m1 - nm1);
        m0 = nm0; m1 = nm1;
        float sum0 = 0.f, sum1 = 0.f;
        #pragma unroll
        for (int j = 0; j < 16; j++) {
            s[j][0] = __expf(s[j][0] - m0);
            s[j][1] = __expf(s[j][1] - m0);
            s[j][2] = __expf(s[j][2] - m1);
            s[j][3] = __expf(s[j][3] - m1);
            sum0 += s[j][0] + s[j][1];
            sum1 += s[j][2] + s[j][3];
        }
        sum0 += __shfl_xor_sync(0xFFFFFFFFu, sum0, 1);
        sum0 += __shfl_xor_sync(0xFFFFFFFFu, sum0, 2);
        sum1 += __shfl_xor_sync(0xFFFFFFFFu, sum1, 1);
        sum1 += __shfl_xor_sync(0xFFFFFFFFu, sum1, 2);
        l0 = l0 * f0 + sum0;
        l1 = l1 * f1 + sum1;
        #pragma unroll
        for (int nj = 0; nj < 8; nj++) {
            O[nj][0] *= f0; O[nj][1] *= f0; O[nj][2] *= f1; O[nj][3] *= f1;
        }

        // O += P @ V   (P C-frag repacks directly into A-frag)
        #pragma unroll
        for (int tt = 0; tt < 8; tt++) {
            unsigned pa[4];
            pa[0] = pack_bf16(s[2*tt    ][0], s[2*tt    ][1]);
            pa[1] = pack_bf16(s[2*tt    ][2], s[2*tt    ][3]);
            pa[2] = pack_bf16(s[2*tt + 1][0], s[2*tt + 1][1]);
            pa[3] = pack_bf16(s[2*tt + 1][2], s[2*tt + 1][3]);
            #pragma unroll
            for (int nj = 0; nj < 8; nj++) {
                unsigned b0 = *reinterpret_cast<unsigned*>(&sVt[nj*8 + g][tt*16 + 2*tg    ]);
                unsigned b1 = *reinterpret_cast<unsigned*>(&sVt[nj*8 + g][tt*16 + 2*tg + 8]);
                mma_bf16(O[nj], pa, b0, b1);
            }
        }
    }

    float r0 = 1.f / l0, r1 = 1.f / l1;
    size_t orow = qrow0 + w * 16 + g;
    #pragma unroll
    for (int nj = 0; nj < 8; nj++) {
        int col = h * 64 + nj * 8 + 2 * tg;
        *reinterpret_cast<float2*>(g_attn + orow * EN + col) =
            make_float2(O[nj][0] * r0, O[nj][1] * r0);
        *reinterpret_cast<float2*>(g_attn + (orow + 8) * EN + col) =
            make_float2(O[nj][2] * r1, O[nj][3] * r1);
    }
}

// ---------------- launch -----------------------------------------------------
extern "C" void kernel_launch(void* const* d_in, const int* in_sizes, int n_in,
                              void* d_out, int out_size) {
    const float* x     = (const float*)d_in[0];
    const unsigned* mask = (const unsigned*)d_in[1];   // bool -> 32-bit (int32/f32)
    const float* ln1_s = (const float*)d_in[2];
    const float* ln1_b = (const float*)d_in[3];
    const float* Wqkv  = (const float*)d_in[4];
    const float* bqkv  = (const float*)d_in[5];
    const float* Wo    = (const float*)d_in[6];
    const float* bo    = (const float*)d_in[7];
    const float* ln2_s = (const float*)d_in[8];
    const float* ln2_b = (const float*)d_in[9];
    const float* lnf_s = (const float*)d_in[10];
    const float* lnf_b = (const float*)d_in[11];
    const float* W1    = (const float*)d_in[12];
    const float* b1    = (const float*)d_in[13];
    const float* W2    = (const float*)d_in[14];
    const float* b2    = (const float*)d_in[15];
    float* out = (float*)d_out;

    float *p_h, *p_qkv, *p_attn, *p_x1, *p_h2, *p_ff;
    cudaGetSymbolAddress((void**)&p_h,    g_h);
    cudaGetSymbolAddress((void**)&p_qkv,  g_qkv);
    cudaGetSymbolAddress((void**)&p_attn, g_attn);
    cudaGetSymbolAddress((void**)&p_x1,   g_x1);
    cudaGetSymbolAddress((void**)&p_h2,   g_h2);
    cudaGetSymbolAddress((void**)&p_ff,   g_ff);

    // 1. h = LN1(x)
    ln1_k<<<ROWS, 256>>>(x, ln1_s, ln1_b, p_h);
    // 2. qkv = h @ Wqkv + bqkv
    gemm_k<EPI_BIAS><<<dim3(3*EN/128, ROWS/128), 256>>>(ROWS, 3*EN, EN, p_h, Wqkv, bqkv, nullptr, p_qkv);
    // 3. attention
    attn_k<<<dim3(LL/64, NB*HHH), 128>>>(mask);
    // 4. x1 = x + attn @ Wo + bo
    gemm_k<EPI_RES><<<dim3(EN/128, ROWS/128), 256>>>(ROWS, EN, EN, p_attn, Wo, bo, x, p_x1);
    // 5. h2 = LNf(LN2(x1))
    ln2f_k<<<ROWS, 256>>>(p_x1, ln2_s, ln2_b, lnf_s, lnf_b, p_h2);
    // 6. ff = gelu(h2 @ W1 + b1)
    gemm_k<EPI_GELU><<<dim3(DFFN/128, ROWS/128), 256>>>(ROWS, DFFN, EN, p_h2, W1, b1, nullptr, p_ff);
    // 7. out = x1 + ff @ W2 + b2
    gemm_k<EPI_RES><<<dim3(EN/128, ROWS/128), 256>>>(ROWS, EN, DFFN, p_ff, W2, b2, p_x1, out);
}

// round 3
// speedup vs baseline: 1.1278x; 1.1278x over previous
#include <cuda_runtime.h>
#include <cuda_bf16.h>

#define EN   1024
#define DFFN 4096
#define NB   2
#define LL   2048
#define HHH  16
#define DDD  64
#define ROWS (NB*LL)   // 4096

// ---------------- scratch (device globals; no allocation allowed) ----------
__device__ float g_h   [ROWS*EN];
__device__ float g_qkv [ROWS*3*EN];
__device__ float g_attn[ROWS*EN];
__device__ float g_x1  [ROWS*EN];
__device__ float g_h2  [ROWS*EN];
__device__ float g_ff  [ROWS*DFFN];

// ---------------- helpers ---------------------------------------------------
__device__ __forceinline__ void mma_tf32(float* c, const unsigned* a, unsigned b0, unsigned b1) {
    asm volatile(
        "mma.sync.aligned.m16n8k8.row.col.f32.tf32.tf32.f32 "
        "{%0,%1,%2,%3},{%4,%5,%6,%7},{%8,%9},{%0,%1,%2,%3};"
        : "+f"(c[0]), "+f"(c[1]), "+f"(c[2]), "+f"(c[3])
        : "r"(a[0]), "r"(a[1]), "r"(a[2]), "r"(a[3]), "r"(b0), "r"(b1));
}

__device__ __forceinline__ void mma_bf16(float* c, const unsigned* a, unsigned b0, unsigned b1) {
    asm volatile(
        "mma.sync.aligned.m16n8k16.row.col.f32.bf16.bf16.f32 "
        "{%0,%1,%2,%3},{%4,%5,%6,%7},{%8,%9},{%0,%1,%2,%3};"
        : "+f"(c[0]), "+f"(c[1]), "+f"(c[2]), "+f"(c[3])
        : "r"(a[0]), "r"(a[1]), "r"(a[2]), "r"(a[3]), "r"(b0), "r"(b1));
}

__device__ __forceinline__ unsigned pack_bf16(float lo, float hi) {
    __nv_bfloat162 p = __floats2bfloat162_rn(lo, hi);
    return *reinterpret_cast<unsigned*>(&p);
}

__device__ __forceinline__ void cpa16(unsigned dst, const float* src) {
    asm volatile("cp.async.cg.shared.global [%0], [%1], 16;\n" :: "r"(dst), "l"(src));
}
#define CP_COMMIT() asm volatile("cp.async.commit_group;\n" ::)
#define CP_WAIT0()  asm volatile("cp.async.wait_group 0;\n" ::)

// block = 256 threads (8 warps). Reduces (a,b) across the block.
__device__ __forceinline__ void blockReduce2(float& a, float& b) {
    __shared__ float sm[16];
    #pragma unroll
    for (int o = 16; o; o >>= 1) {
        a += __shfl_xor_sync(0xFFFFFFFFu, a, o);
        b += __shfl_xor_sync(0xFFFFFFFFu, b, o);
    }
    int w = threadIdx.x >> 5, lane = threadIdx.x & 31;
    __syncthreads();
    if (lane == 0) { sm[w] = a; sm[8 + w] = b; }
    __syncthreads();
    a = 0.f; b = 0.f;
    #pragma unroll
    for (int i = 0; i < 8; i++) { a += sm[i]; b += sm[8 + i]; }
}

// ---------------- LN1 --------------------------------------------------------
__global__ __launch_bounds__(256) void ln1_k(const float* __restrict__ x,
                                             const float* __restrict__ s,
                                             const float* __restrict__ b,
                                             float* __restrict__ out) {
    int row = blockIdx.x, t = threadIdx.x;
    float4 v = reinterpret_cast<const float4*>(x + (size_t)row * EN)[t];
    float sum = v.x + v.y + v.z + v.w;
    float sq  = v.x*v.x + v.y*v.y + v.z*v.z + v.w*v.w;
    blockReduce2(sum, sq);
    float mu = sum * (1.f / EN);
    float rs = rsqrtf(sq * (1.f / EN) - mu * mu + 1e-5f);
    float4 sv = reinterpret_cast<const float4*>(s)[t];
    float4 bv = reinterpret_cast<const float4*>(b)[t];
    float4 o;
    o.x = (v.x - mu) * rs * sv.x + bv.x;
    o.y = (v.y - mu) * rs * sv.y + bv.y;
    o.z = (v.z - mu) * rs * sv.z + bv.z;
    o.w = (v.w - mu) * rs * sv.w + bv.w;
    reinterpret_cast<float4*>(out + (size_t)row * EN)[t] = o;
}

// ---------------- LN2 then LNf fused ----------------------------------------
__global__ __launch_bounds__(256) void ln2f_k(const float* __restrict__ x,
                                              const float* __restrict__ s2,
                                              const float* __restrict__ b2,
                                              const float* __restrict__ sf,
                                              const float* __restrict__ bf,
                                              float* __restrict__ out) {
    int row = blockIdx.x, t = threadIdx.x;
    float4 v = reinterpret_cast<const float4*>(x + (size_t)row * EN)[t];
    float sum = v.x + v.y + v.z + v.w;
    float sq  = v.x*v.x + v.y*v.y + v.z*v.z + v.w*v.w;
    blockReduce2(sum, sq);
    float mu = sum * (1.f / EN);
    float rs = rsqrtf(sq * (1.f / EN) - mu * mu + 1e-5f);
    float4 sv = reinterpret_cast<const float4*>(s2)[t];
    float4 bv = reinterpret_cast<const float4*>(b2)[t];
    float4 y;
    y.x = (v.x - mu) * rs * sv.x + bv.x;
    y.y = (v.y - mu) * rs * sv.y + bv.y;
    y.z = (v.z - mu) * rs * sv.z + bv.z;
    y.w = (v.w - mu) * rs * sv.w + bv.w;
    float sum2 = y.x + y.y + y.z + y.w;
    float sq2  = y.x*y.x + y.y*y.y + y.z*y.z + y.w*y.w;
    blockReduce2(sum2, sq2);
    float mu2 = sum2 * (1.f / EN);
    float rs2 = rsqrtf(sq2 * (1.f / EN) - mu2 * mu2 + 1e-5f);
    float4 fv = reinterpret_cast<const float4*>(sf)[t];
    float4 gv = reinterpret_cast<const float4*>(bf)[t];
    float4 o;
    o.x = (y.x - mu2) * rs2 * fv.x + gv.x;
    o.y = (y.y - mu2) * rs2 * fv.y + gv.y;
    o.z = (y.z - mu2) * rs2 * fv.z + gv.z;
    o.w = (y.w - mu2) * rs2 * fv.w + gv.w;
    reinterpret_cast<float4*>(out + (size_t)row * EN)[t] = o;
}

// ---------------- tf32 GEMM v2: cp.async double-buffered --------------------
// A [M,K] row-major fp32, B [K,N] row-major fp32. BM=BN=128, BK=32.
// 128 threads (4 warps in 2x2), warp tile 64x64. fp32 bits fed to tf32 MMA
// directly (RZ truncation, no cvt pass).
#define EPI_BIAS 0
#define EPI_GELU 1
#define EPI_RES  2

#define SA_STRIDE 36
#define SB_STRIDE 132
#define SA_ELEMS  (128*SA_STRIDE)   // 4608
#define SB_ELEMS  (32*SB_STRIDE)    // 4224
#define STG_ELEMS (SA_ELEMS+SB_ELEMS)
#define GEMM_SMEM (2*STG_ELEMS*4)   // 70656 bytes

template <int EPI>
__global__ __launch_bounds__(128, 2) void gemm2_k(int M, int N, int K,
                                                  const float* __restrict__ A,
                                                  const float* __restrict__ B,
                                                  const float* __restrict__ bias,
                                                  const float* __restrict__ res,
                                                  float* __restrict__ C) {
    extern __shared__ float sm[];
    int bm = blockIdx.y * 128, bn = blockIdx.x * 128;
    int t = threadIdx.x, wid = t >> 5, lane = t & 31;
    int g = lane >> 2, tg = lane & 3;
    int wr = (wid & 1) * 64;        // warp row base
    int wc = (wid >> 1) * 64;       // warp col base

    float c[4][8][4];
    #pragma unroll
    for (int mi = 0; mi < 4; mi++)
        #pragma unroll
        for (int nj = 0; nj < 8; nj++)
            #pragma unroll
            for (int q = 0; q < 4; q++) c[mi][nj][q] = 0.f;

    const float* Ab = A + (size_t)bm * K;
    const float* Bb = B + bn;

    // prefetch lambda: tile kt -> stage s
    auto prefetch = [&](int kt, int s) {
        float* dA = sm + s * STG_ELEMS;
        float* dB = dA + SA_ELEMS;
        int k0 = kt * 32;
        #pragma unroll
        for (int i = 0; i < 8; i++) {
            int id = i * 128 + t;
            int r = id >> 3, c4 = (id & 7) * 4;
            unsigned dst = (unsigned)__cvta_generic_to_shared(dA + r * SA_STRIDE + c4);
            cpa16(dst, Ab + (size_t)r * K + k0 + c4);
        }
        #pragma unroll
        for (int i = 0; i < 8; i++) {
            int id = i * 128 + t;
            int r = id >> 5, c4 = (id & 31) * 4;
            unsigned dst = (unsigned)__cvta_generic_to_shared(dB + r * SB_STRIDE + c4);
            cpa16(dst, Bb + (size_t)(k0 + r) * N + c4);
        }
    };

    int T = K >> 5;
    prefetch(0, 0);
    CP_COMMIT();

    for (int kt = 0; kt < T; kt++) {
        int s = kt & 1;
        CP_WAIT0();
        __syncthreads();
        if (kt + 1 < T) { prefetch(kt + 1, s ^ 1); CP_COMMIT(); }

        const float* cA = sm + s * STG_ELEMS;
        const float* cB = cA + SA_ELEMS;
        #pragma unroll
        for (int kk = 0; kk < 32; kk += 8) {
            unsigned a[4][4], b[8][2];
            #pragma unroll
            for (int mi = 0; mi < 4; mi++) {
                int r = wr + mi * 16 + g;
                a[mi][0] = __float_as_uint(cA[(r    ) * SA_STRIDE + kk + tg    ]);
                a[mi][1] = __float_as_uint(cA[(r + 8) * SA_STRIDE + kk + tg    ]);
                a[mi][2] = __float_as_uint(cA[(r    ) * SA_STRIDE + kk + tg + 4]);
                a[mi][3] = __float_as_uint(cA[(r + 8) * SA_STRIDE + kk + tg + 4]);
            }
            #pragma unroll
            for (int nj = 0; nj < 8; nj++) {
                int cc = wc + nj * 8 + g;
                b[nj][0] = __float_as_uint(cB[(kk + tg    ) * SB_STRIDE + cc]);
                b[nj][1] = __float_as_uint(cB[(kk + tg + 4) * SB_STRIDE + cc]);
            }
            #pragma unroll
            for (int mi = 0; mi < 4; mi++)
                #pragma unroll
                for (int nj = 0; nj < 8; nj++)
                    mma_tf32(c[mi][nj], a[mi], b[nj][0], b[nj][1]);
        }
    }

    // epilogue
    #pragma unroll
    for (int mi = 0; mi < 4; mi++) {
        #pragma unroll
        for (int nj = 0; nj < 8; nj++) {
            int row = bm + wr + mi * 16 + g;
            int col = bn + wc + nj * 8 + tg * 2;
            float b0 = bias[col], b1 = bias[col + 1];
            float v0 = c[mi][nj][0] + b0, v1 = c[mi][nj][1] + b1;
            float v2 = c[mi][nj][2] + b0, v3 = c[mi][nj][3] + b1;
            if (EPI == EPI_GELU) {
                v0 = 0.5f * v0 * (1.f + erff(v0 * 0.70710678118f));
                v1 = 0.5f * v1 * (1.f + erff(v1 * 0.70710678118f));
                v2 = 0.5f * v2 * (1.f + erff(v2 * 0.70710678118f));
                v3 = 0.5f * v3 * (1.f + erff(v3 * 0.70710678118f));
            }
            if (EPI == EPI_RES) {
                float2 r0 = *reinterpret_cast<const float2*>(res + (size_t)row * N + col);
                float2 r1 = *reinterpret_cast<const float2*>(res + (size_t)(row + 8) * N + col);
                v0 += r0.x; v1 += r0.y; v2 += r1.x; v3 += r1.y;
            }
            *reinterpret_cast<float2*>(C + (size_t)row * N + col)       = make_float2(v0, v1);
            *reinterpret_cast<float2*>(C + (size_t)(row + 8) * N + col) = make_float2(v2, v3);
        }
    }
}

// ---------------- bf16 flash attention (no online max: scores bounded) ------
// grid (L/64 q-tiles, N*H); block 128 (4 warps, 16 q-rows/warp). KV tile 128.
// Mask: 32-bit words, nonzero => masked => p = 0.
__global__ __launch_bounds__(128) void attn_k(const unsigned* __restrict__ mask) {
    __shared__ __nv_bfloat16 sQ [64][72];
    __shared__ __nv_bfloat16 sK [128][72];
    __shared__ __nv_bfloat16 sVt[64][136];

    int t = threadIdx.x, w = t >> 5, lane = t & 31;
    int g = lane >> 2, tg = lane & 3;
    int qt = blockIdx.x, nh = blockIdx.y;
    int n = nh >> 4, h = nh & 15;
    size_t qrow0 = (size_t)n * LL + (size_t)qt * 64;

    #pragma unroll
    for (int i = 0; i < 8; i++) {
        int id = t + i * 128;
        int r = id >> 4, c4 = (id & 15) * 4;
        float4 v = *reinterpret_cast<const float4*>(g_qkv + (qrow0 + r) * 3072 + h * 64 + c4);
        sQ[r][c4 + 0] = __float2bfloat16(v.x * 0.125f);
        sQ[r][c4 + 1] = __float2bfloat16(v.y * 0.125f);
        sQ[r][c4 + 2] = __float2bfloat16(v.z * 0.125f);
        sQ[r][c4 + 3] = __float2bfloat16(v.w * 0.125f);
    }
    __syncthreads();

    unsigned aQ[4][4];
    #pragma unroll
    for (int tt = 0; tt < 4; tt++) {
        aQ[tt][0] = *reinterpret_cast<unsigned*>(&sQ[w*16 + g    ][tt*16 + 2*tg    ]);
        aQ[tt][1] = *reinterpret_cast<unsigned*>(&sQ[w*16 + g + 8][tt*16 + 2*tg    ]);
        aQ[tt][2] = *reinterpret_cast<unsigned*>(&sQ[w*16 + g    ][tt*16 + 2*tg + 8]);
        aQ[tt][3] = *reinterpret_cast<unsigned*>(&sQ[w*16 + g + 8][tt*16 + 2*tg + 8]);
    }

    float O[8][4];
    #pragma unroll
    for (int nj = 0; nj < 8; nj++)
        #pragma unroll
        for (int q = 0; q < 4; q++) O[nj][q] = 0.f;
    float l0 = 0.f, l1 = 0.f;

    size_t mrow = (size_t)nh * LL + (size_t)qt * 64 + w * 16;

    for (int kv0 = 0; kv0 < LL; kv0 += 128) {
        __syncthreads();
        #pragma unroll
        for (int i = 0; i < 16; i++) {
            int id = t + i * 128;
            int r = id >> 4, c4 = (id & 15) * 4;
            size_t base = ((size_t)n * LL + kv0 + r) * 3072 + h * 64 + c4;
            float4 kv = *reinterpret_cast<const float4*>(g_qkv + base + 1024);
            sK[r][c4 + 0] = __float2bfloat16(kv.x);
            sK[r][c4 + 1] = __float2bfloat16(kv.y);
            sK[r][c4 + 2] = __float2bfloat16(kv.z);
            sK[r][c4 + 3] = __float2bfloat16(kv.w);
            float4 vv = *reinterpret_cast<const float4*>(g_qkv + base + 2048);
            sVt[c4 + 0][r] = __float2bfloat16(vv.x);
            sVt[c4 + 1][r] = __float2bfloat16(vv.y);
            sVt[c4 + 2][r] = __float2bfloat16(vv.z);
            sVt[c4 + 3][r] = __float2bfloat16(vv.w);
        }
        __syncthreads();

        // S = Q K^T
        float s[16][4];
        #pragma unroll
        for (int j = 0; j < 16; j++) {
            s[j][0] = s[j][1] = s[j][2] = s[j][3] = 0.f;
            #pragma unroll
            for (int tt = 0; tt < 4; tt++) {
                unsigned b0 = *reinterpret_cast<unsigned*>(&sK[j*8 + g][tt*16 + 2*tg    ]);
                unsigned b1 = *reinterpret_cast<unsigned*>(&sK[j*8 + g][tt*16 + 2*tg + 8]);
                mma_bf16(s[j], aQ[tt], b0, b1);
            }
        }

        // p = mask ? 0 : exp(s); accumulate row sums
        const unsigned* mr0 = mask + (mrow + g)     * (size_t)LL + kv0;
        const unsigned* mr1 = mask + (mrow + g + 8) * (size_t)LL + kv0;
        #pragma unroll
        for (int j = 0; j < 16; j++) {
            int col = j * 8 + 2 * tg;
            uint2 p0 = *reinterpret_cast<const uint2*>(mr0 + col);
            uint2 p1 = *reinterpret_cast<const uint2*>(mr1 + col);
            s[j][0] = p0.x ? 0.f : __expf(s[j][0]);
            s[j][1] = p0.y ? 0.f : __expf(s[j][1]);
            s[j][2] = p1.x ? 0.f : __expf(s[j][2]);
            s[j][3] = p1.y ? 0.f : __expf(s[j][3]);
            l0 += s[j][0] + s[j][1];
            l1 += s[j][2] + s[j][3];
        }

        // O += P @ V
        #pragma unroll
        for (int tt = 0; tt < 8; tt++) {
            unsigned pa[4];
            pa[0] = pack_bf16(s[2*tt    ][0], s[2*tt    ][1]);
            pa[1] = pack_bf16(s[2*tt    ][2], s[2*tt    ][3]);
            pa[2] = pack_bf16(s[2*tt + 1][0], s[2*tt + 1][1]);
            pa[3] = pack_bf16(s[2*tt + 1][2], s[2*tt + 1][3]);
            #pragma unroll
            for (int nj = 0; nj < 8; nj++) {
                unsigned b0 = *reinterpret_cast<unsigned*>(&sVt[nj*8 + g][tt*16 + 2*tg    ]);
                unsigned b1 = *reinterpret_cast<unsigned*>(&sVt[nj*8 + g][tt*16 + 2*tg + 8]);
                mma_bf16(O[nj], pa, b0, b1);
            }
        }
    }

    // final row-sum reduction over tg lanes, then normalize
    l0 += __shfl_xor_sync(0xFFFFFFFFu, l0, 1);
    l0 += __shfl_xor_sync(0xFFFFFFFFu, l0, 2);
    l1 += __shfl_xor_sync(0xFFFFFFFFu, l1, 1);
    l1 += __shfl_xor_sync(0xFFFFFFFFu, l1, 2);
    float r0 = 1.f / l0, r1 = 1.f / l1;
    size_t orow = qrow0 + w * 16 + g;
    #pragma unroll
    for (int nj = 0; nj < 8; nj++) {
        int col = h * 64 + nj * 8 + 2 * tg;
        *reinterpret_cast<float2*>(g_attn + orow * EN + col) =
            make_float2(O[nj][0] * r0, O[nj][1] * r0);
        *reinterpret_cast<float2*>(g_attn + (orow + 8) * EN + col) =
            make_float2(O[nj][2] * r1, O[nj][3] * r1);
    }
}

// ---------------- launch -----------------------------------------------------
extern "C" void kernel_launch(void* const* d_in, const int* in_sizes, int n_in,
                              void* d_out, int out_size) {
    const float* x     = (const float*)d_in[0];
    const unsigned* mask = (const unsigned*)d_in[1];
    const float* ln1_s = (const float*)d_in[2];
    const float* ln1_b = (const float*)d_in[3];
    const float* Wqkv  = (const float*)d_in[4];
    const float* bqkv  = (const float*)d_in[5];
    const float* Wo    = (const float*)d_in[6];
    const float* bo    = (const float*)d_in[7];
    const float* ln2_s = (const float*)d_in[8];
    const float* ln2_b = (const float*)d_in[9];
    const float* lnf_s = (const float*)d_in[10];
    const float* lnf_b = (const float*)d_in[11];
    const float* W1    = (const float*)d_in[12];
    const float* b1    = (const float*)d_in[13];
    const float* W2    = (const float*)d_in[14];
    const float* b2    = (const float*)d_in[15];
    float* out = (float*)d_out;

    float *p_h, *p_qkv, *p_attn, *p_x1, *p_h2, *p_ff;
    cudaGetSymbolAddress((void**)&p_h,    g_h);
    cudaGetSymbolAddress((void**)&p_qkv,  g_qkv);
    cudaGetSymbolAddress((void**)&p_attn, g_attn);
    cudaGetSymbolAddress((void**)&p_x1,   g_x1);
    cudaGetSymbolAddress((void**)&p_h2,   g_h2);
    cudaGetSymbolAddress((void**)&p_ff,   g_ff);

    static int smem_set = 0;
    if (!smem_set) {
        cudaFuncSetAttribute(gemm2_k<EPI_BIAS>, cudaFuncAttributeMaxDynamicSharedMemorySize, GEMM_SMEM);
        cudaFuncSetAttribute(gemm2_k<EPI_GELU>, cudaFuncAttributeMaxDynamicSharedMemorySize, GEMM_SMEM);
        cudaFuncSetAttribute(gemm2_k<EPI_RES>,  cudaFuncAttributeMaxDynamicSharedMemorySize, GEMM_SMEM);
        smem_set = 1;
    }

    // 1. h = LN1(x)
    ln1_k<<<ROWS, 256>>>(x, ln1_s, ln1_b, p_h);
    // 2. qkv = h @ Wqkv + bqkv
    gemm2_k<EPI_BIAS><<<dim3(3*EN/128, ROWS/128), 128, GEMM_SMEM>>>(ROWS, 3*EN, EN, p_h, Wqkv, bqkv, nullptr, p_qkv);
    // 3. attention
    attn_k<<<dim3(LL/64, NB*HHH), 128>>>(mask);
    // 4. x1 = x + attn @ Wo + bo
    gemm2_k<EPI_RES><<<dim3(EN/128, ROWS/128), 128, GEMM_SMEM>>>(ROWS, EN, EN, p_attn, Wo, bo, x, p_x1);
    // 5. h2 = LNf(LN2(x1))
    ln2f_k<<<ROWS, 256>>>(p_x1, ln2_s, ln2_b, lnf_s, lnf_b, p_h2);
    // 6. ff = gelu(h2 @ W1 + b1)
    gemm2_k<EPI_GELU><<<dim3(DFFN/128, ROWS/128), 128, GEMM_SMEM>>>(ROWS, DFFN, EN, p_h2, W1, b1, nullptr, p_ff);
    // 7. out = x1 + ff @ W2 + b2
    gemm2_k<EPI_RES><<<dim3(EN/128, ROWS/128), 128, GEMM_SMEM>>>(ROWS, EN, DFFN, p_ff, W2, b2, p_x1, out);
}

// round 4
// speedup vs baseline: 1.2659x; 1.1224x over previous
#include <cuda_runtime.h>
#include <cuda_bf16.h>

#define EN   1024
#define DFFN 4096
#define NB   2
#define LL   2048
#define HHH  16
#define DDD  64
#define ROWS (NB*LL)   // 4096

// ---------------- scratch (device globals; no allocation allowed) ----------
__device__ __nv_bfloat16 g_hb   [ROWS*EN];      // LN1 out (bf16, A of QKV)
__device__ float         g_qkv  [ROWS*3*EN];    // QKV projection
__device__ __nv_bfloat16 g_attnb[ROWS*EN];      // attn out (bf16, A of Wo)
__device__ float         g_x1   [ROWS*EN];      // x + attn@Wo + bo
__device__ float         g_h2   [ROWS*EN];      // LNf(LN2(x1)) (rna-rounded)
__device__ float         g_ff   [ROWS*DFFN];    // gelu(h2@W1+b1) (rna-rounded)
// transposed / converted weights (refreshed every launch)
__device__ __nv_bfloat16 g_Wqkvt[3*EN*EN];      // [3E][E] bf16
__device__ __nv_bfloat16 g_Wot  [EN*EN];        // [E][E]  bf16
__device__ float         g_W1t  [DFFN*EN];      // [DFF][E] tf32-rna
__device__ float         g_W2t  [EN*DFFN];      // [E][DFF] tf32-rna

// ---------------- helpers ---------------------------------------------------
__device__ __forceinline__ float rna(float f) {
    unsigned r;
    asm("cvt.rna.tf32.f32 %0, %1;" : "=r"(r) : "f"(f));
    return __uint_as_float(r);
}

__device__ __forceinline__ void mma_tf32(float* c, const unsigned* a, unsigned b0, unsigned b1) {
    asm volatile(
        "mma.sync.aligned.m16n8k8.row.col.f32.tf32.tf32.f32 "
        "{%0,%1,%2,%3},{%4,%5,%6,%7},{%8,%9},{%0,%1,%2,%3};"
        : "+f"(c[0]), "+f"(c[1]), "+f"(c[2]), "+f"(c[3])
        : "r"(a[0]), "r"(a[1]), "r"(a[2]), "r"(a[3]), "r"(b0), "r"(b1));
}

__device__ __forceinline__ void mma_bf16(float* c, const unsigned* a, unsigned b0, unsigned b1) {
    asm volatile(
        "mma.sync.aligned.m16n8k16.row.col.f32.bf16.bf16.f32 "
        "{%0,%1,%2,%3},{%4,%5,%6,%7},{%8,%9},{%0,%1,%2,%3};"
        : "+f"(c[0]), "+f"(c[1]), "+f"(c[2]), "+f"(c[3])
        : "r"(a[0]), "r"(a[1]), "r"(a[2]), "r"(a[3]), "r"(b0), "r"(b1));
}

__device__ __forceinline__ unsigned pack_bf16(float lo, float hi) {
    __nv_bfloat162 p = __floats2bfloat162_rn(lo, hi);
    return *reinterpret_cast<unsigned*>(&p);
}

__device__ __forceinline__ void cpa16(unsigned dst, const void* src) {
    asm volatile("cp.async.cg.shared.global [%0], [%1], 16;\n" :: "r"(dst), "l"(src));
}
#define CP_COMMIT() asm volatile("cp.async.commit_group;\n" ::)
#define CP_WAIT0()  asm volatile("cp.async.wait_group 0;\n" ::)

__device__ __forceinline__ void blockReduce2(float& a, float& b) {
    __shared__ float sm[16];
    #pragma unroll
    for (int o = 16; o; o >>= 1) {
        a += __shfl_xor_sync(0xFFFFFFFFu, a, o);
        b += __shfl_xor_sync(0xFFFFFFFFu, b, o);
    }
    int w = threadIdx.x >> 5, lane = threadIdx.x & 31;
    __syncthreads();
    if (lane == 0) { sm[w] = a; sm[8 + w] = b; }
    __syncthreads();
    a = 0.f; b = 0.f;
    #pragma unroll
    for (int i = 0; i < 8; i++) { a += sm[i]; b += sm[8 + i]; }
}

// ---------------- weight pre-pass: transpose (+round) ------------------------
// out[n][k] = rna(in[k][n]); grid (N/32, K/32), block (32,8)
__global__ __launch_bounds__(256) void transT_f32_k(const float* __restrict__ in,
                                                    float* __restrict__ out,
                                                    int K, int N) {
    __shared__ float tile[32][33];
    int k0 = blockIdx.y * 32, n0 = blockIdx.x * 32;
    int tx = threadIdx.x, ty = threadIdx.y;
    #pragma unroll
    for (int i = 0; i < 32; i += 8)
        tile[ty + i][tx] = in[(size_t)(k0 + ty + i) * N + n0 + tx];
    __syncthreads();
    #pragma unroll
    for (int i = 0; i < 32; i += 8)
        out[(size_t)(n0 + ty + i) * K + k0 + tx] = rna(tile[tx][ty + i]);
}

__global__ __launch_bounds__(256) void transT_bf16_k(const float* __restrict__ in,
                                                     __nv_bfloat16* __restrict__ out,
                                                     int K, int N) {
    __shared__ float tile[32][33];
    int k0 = blockIdx.y * 32, n0 = blockIdx.x * 32;
    int tx = threadIdx.x, ty = threadIdx.y;
    #pragma unroll
    for (int i = 0; i < 32; i += 8)
        tile[ty + i][tx] = in[(size_t)(k0 + ty + i) * N + n0 + tx];
    __syncthreads();
    #pragma unroll
    for (int i = 0; i < 32; i += 8)
        out[(size_t)(n0 + ty + i) * K + k0 + tx] = __float2bfloat16(tile[tx][ty + i]);
}

// ---------------- LN1: writes bf16 ------------------------------------------
__global__ __launch_bounds__(256) void ln1_k(const float* __restrict__ x,
                                             const float* __restrict__ s,
                                             const float* __restrict__ b,
                                             __nv_bfloat16* __restrict__ out) {
    int row = blockIdx.x, t = threadIdx.x;
    float4 v = reinterpret_cast<const float4*>(x + (size_t)row * EN)[t];
    float sum = v.x + v.y + v.z + v.w;
    float sq  = v.x*v.x + v.y*v.y + v.z*v.z + v.w*v.w;
    blockReduce2(sum, sq);
    float mu = sum * (1.f / EN);
    float rs = rsqrtf(sq * (1.f / EN) - mu * mu + 1e-5f);
    float4 sv = reinterpret_cast<const float4*>(s)[t];
    float4 bv = reinterpret_cast<const float4*>(b)[t];
    uint2 pk;
    pk.x = pack_bf16((v.x - mu) * rs * sv.x + bv.x, (v.y - mu) * rs * sv.y + bv.y);
    pk.y = pack_bf16((v.z - mu) * rs * sv.z + bv.z, (v.w - mu) * rs * sv.w + bv.w);
    reinterpret_cast<uint2*>(out + (size_t)row * EN)[t] = pk;
}

// ---------------- LN2 then LNf fused: writes rna fp32 ------------------------
__global__ __launch_bounds__(256) void ln2f_k(const float* __restrict__ x,
                                              const float* __restrict__ s2,
                                              const float* __restrict__ b2,
                                              const float* __restrict__ sf,
                                              const float* __restrict__ bf,
                                              float* __restrict__ out) {
    int row = blockIdx.x, t = threadIdx.x;
    float4 v = reinterpret_cast<const float4*>(x + (size_t)row * EN)[t];
    float sum = v.x + v.y + v.z + v.w;
    float sq  = v.x*v.x + v.y*v.y + v.z*v.z + v.w*v.w;
    blockReduce2(sum, sq);
    float mu = sum * (1.f / EN);
    float rs = rsqrtf(sq * (1.f / EN) - mu * mu + 1e-5f);
    float4 sv = reinterpret_cast<const float4*>(s2)[t];
    float4 bv = reinterpret_cast<const float4*>(b2)[t];
    float4 y;
    y.x = (v.x - mu) * rs * sv.x + bv.x;
    y.y = (v.y - mu) * rs * sv.y + bv.y;
    y.z = (v.z - mu) * rs * sv.z + bv.z;
    y.w = (v.w - mu) * rs * sv.w + bv.w;
    float sum2 = y.x + y.y + y.z + y.w;
    float sq2  = y.x*y.x + y.y*y.y + y.z*y.z + y.w*y.w;
    blockReduce2(sum2, sq2);
    float mu2 = sum2 * (1.f / EN);
    float rs2 = rsqrtf(sq2 * (1.f / EN) - mu2 * mu2 + 1e-5f);
    float4 fv = reinterpret_cast<const float4*>(sf)[t];
    float4 gv = reinterpret_cast<const float4*>(bf)[t];
    float4 o;
    o.x = rna((y.x - mu2) * rs2 * fv.x + gv.x);
    o.y = rna((y.y - mu2) * rs2 * fv.y + gv.y);
    o.z = rna((y.z - mu2) * rs2 * fv.z + gv.z);
    o.w = rna((y.w - mu2) * rs2 * fv.w + gv.w);
    reinterpret_cast<float4*>(out + (size_t)row * EN)[t] = o;
}

// ---------------- unified GEMM: C = epi(A@Bt^T + bias [+res]) ----------------
// A [M][K] row-major (T = float pre-rounded, or bf16). Bt [N][K] row-major
// (pre-transposed weights). BM=BN=128, BK = 32 words (32 f32 / 64 bf16).
// 128 threads, 4 warps 2x2, warp tile 64x64. pi-permuted k-groups so every
// fragment load is one LDS.128. Strides 48 words (=16 mod 32): conflict-free.
#define EPI_BIAS 0
#define EPI_GELU 1
#define EPI_RES  2

#define STG_WORDS (2*128*48)        // A-half + B-half
#define GEMM_SMEM (2*STG_WORDS*4)   // 98304 bytes, 2 stages

template <int EPI, typename T>
__global__ __launch_bounds__(128, 2) void gemm3_k(int M, int N, int K,
                                                  const T* __restrict__ A,
                                                  const T* __restrict__ Bt,
                                                  const float* __restrict__ bias,
                                                  const float* __restrict__ res,
                                                  float* __restrict__ C) {
    extern __shared__ float smem[];
    constexpr int EV  = 16 / sizeof(T);   // elems per 16B
    constexpr int BKE = 32 * EV / 4;      // elems of K per tile (32 f32 / 64 bf16)
    int bm = blockIdx.y * 128, bn = blockIdx.x * 128;
    int t = threadIdx.x, wid = t >> 5, lane = t & 31;
    int g = lane >> 2, tg = lane & 3;
    int wr = (wid & 1) * 64;
    int wc = (wid >> 1) * 64;

    float c[4][8][4];
    #pragma unroll
    for (int mi = 0; mi < 4; mi++)
        #pragma unroll
        for (int nj = 0; nj < 8; nj++)
            #pragma unroll
            for (int q = 0; q < 4; q++) c[mi][nj][q] = 0.f;

    const T* Ab = A  + (size_t)bm * K;
    const T* Bb = Bt + (size_t)bn * K;
    int r8 = t >> 3, c8 = t & 7;    // 128 rows x 8 chunks per 1024-id block

    auto prefetch = [&](int kt, int s) {
        float* dA = smem + s * STG_WORDS;
        float* dB = dA + 128 * 48;
        size_t kofs = (size_t)kt * BKE + c8 * EV;
        unsigned da = (unsigned)__cvta_generic_to_shared(dA + r8 * 48 + c8 * 4);
        unsigned db = (unsigned)__cvta_generic_to_shared(dB + r8 * 48 + c8 * 4);
        #pragma unroll
        for (int i = 0; i < 8; i++) {
            cpa16(da + i * 16 * 48 * 4, Ab + (size_t)(r8 + i * 16) * K + kofs);
            cpa16(db + i * 16 * 48 * 4, Bb + (size_t)(r8 + i * 16) * K + kofs);
        }
    };

    int Tn = K / BKE;
    prefetch(0, 0);
    CP_COMMIT();

    for (int kt = 0; kt < Tn; kt++) {
        int s = kt & 1;
        CP_WAIT0();
        __syncthreads();
        if (kt + 1 < Tn) { prefetch(kt + 1, s ^ 1); CP_COMMIT(); }

        const float* cA = smem + s * STG_WORDS;
        const float* cB = cA + 128 * 48;
        #pragma unroll
        for (int u = 0; u < 2; u++) {
            uint4 aF[8], bF[8];
            #pragma unroll
            for (int i = 0; i < 8; i++) {
                int r = wr + (i >> 1) * 16 + g + (i & 1) * 8;
                aF[i] = *reinterpret_cast<const uint4*>(cA + r * 48 + u * 16 + tg * 4);
            }
            #pragma unroll
            for (int nj = 0; nj < 8; nj++) {
                int cc = wc + nj * 8 + g;
                bF[nj] = *reinterpret_cast<const uint4*>(cB + cc * 48 + u * 16 + tg * 4);
            }
            #pragma unroll
            for (int mi = 0; mi < 4; mi++) {
                unsigned ae[4] = {aF[2*mi].x, aF[2*mi+1].x, aF[2*mi].y, aF[2*mi+1].y};
                unsigned ao[4] = {aF[2*mi].z, aF[2*mi+1].z, aF[2*mi].w, aF[2*mi+1].w};
                #pragma unroll
                for (int nj = 0; nj < 8; nj++) {
                    if (sizeof(T) == 2) {
                        mma_bf16(c[mi][nj], ae, bF[nj].x, bF[nj].y);
                        mma_bf16(c[mi][nj], ao, bF[nj].z, bF[nj].w);
                    } else {
                        mma_tf32(c[mi][nj], ae, bF[nj].x, bF[nj].y);
                        mma_tf32(c[mi][nj], ao, bF[nj].z, bF[nj].w);
                    }
                }
            }
        }
    }

    #pragma unroll
    for (int mi = 0; mi < 4; mi++) {
        #pragma unroll
        for (int nj = 0; nj < 8; nj++) {
            int row = bm + wr + mi * 16 + g;
            int col = bn + wc + nj * 8 + tg * 2;
            float b0 = bias[col], b1 = bias[col + 1];
            float v0 = c[mi][nj][0] + b0, v1 = c[mi][nj][1] + b1;
            float v2 = c[mi][nj][2] + b0, v3 = c[mi][nj][3] + b1;
            if (EPI == EPI_GELU) {
                v0 = rna(0.5f * v0 * (1.f + erff(v0 * 0.70710678118f)));
                v1 = rna(0.5f * v1 * (1.f + erff(v1 * 0.70710678118f)));
                v2 = rna(0.5f * v2 * (1.f + erff(v2 * 0.70710678118f)));
                v3 = rna(0.5f * v3 * (1.f + erff(v3 * 0.70710678118f)));
            }
            if (EPI == EPI_RES) {
                float2 r0 = *reinterpret_cast<const float2*>(res + (size_t)row * N + col);
                float2 r1 = *reinterpret_cast<const float2*>(res + (size_t)(row + 8) * N + col);
                v0 += r0.x; v1 += r0.y; v2 += r1.x; v3 += r1.y;
            }
            *reinterpret_cast<float2*>(C + (size_t)row * N + col)       = make_float2(v0, v1);
            *reinterpret_cast<float2*>(C + (size_t)(row + 8) * N + col) = make_float2(v2, v3);
        }
    }
}

// ---------------- bf16 flash attention (unnormalized accumulate) -------------
__global__ __launch_bounds__(128) void attn_k(const unsigned* __restrict__ mask) {
    __shared__ __nv_bfloat16 sQ [64][72];
    __shared__ __nv_bfloat16 sK [128][72];
    __shared__ __nv_bfloat16 sVt[64][136];

    int t = threadIdx.x, w = t >> 5, lane = t & 31;
    int g = lane >> 2, tg = lane & 3;
    int qt = blockIdx.x, nh = blockIdx.y;
    int n = nh >> 4, h = nh & 15;
    size_t qrow0 = (size_t)n * LL + (size_t)qt * 64;

    #pragma unroll
    for (int i = 0; i < 8; i++) {
        int id = t + i * 128;
        int r = id >> 4, c4 = (id & 15) * 4;
        float4 v = *reinterpret_cast<const float4*>(g_qkv + (qrow0 + r) * 3072 + h * 64 + c4);
        sQ[r][c4 + 0] = __float2bfloat16(v.x * 0.125f);
        sQ[r][c4 + 1] = __float2bfloat16(v.y * 0.125f);
        sQ[r][c4 + 2] = __float2bfloat16(v.z * 0.125f);
        sQ[r][c4 + 3] = __float2bfloat16(v.w * 0.125f);
    }
    __syncthreads();

    unsigned aQ[4][4];
    #pragma unroll
    for (int tt = 0; tt < 4; tt++) {
        aQ[tt][0] = *reinterpret_cast<unsigned*>(&sQ[w*16 + g    ][tt*16 + 2*tg    ]);
        aQ[tt][1] = *reinterpret_cast<unsigned*>(&sQ[w*16 + g + 8][tt*16 + 2*tg    ]);
        aQ[tt][2] = *reinterpret_cast<unsigned*>(&sQ[w*16 + g    ][tt*16 + 2*tg + 8]);
        aQ[tt][3] = *reinterpret_cast<unsigned*>(&sQ[w*16 + g + 8][tt*16 + 2*tg + 8]);
    }

    float O[8][4];
    #pragma unroll
    for (int nj = 0; nj < 8; nj++)
        #pragma unroll
        for (int q = 0; q < 4; q++) O[nj][q] = 0.f;
    float l0 = 0.f, l1 = 0.f;

    size_t mrow = (size_t)nh * LL + (size_t)qt * 64 + w * 16;

    for (int kv0 = 0; kv0 < LL; kv0 += 128) {
        __syncthreads();
        #pragma unroll
        for (int i = 0; i < 16; i++) {
            int id = t + i * 128;
            int r = id >> 4, c4 = (id & 15) * 4;
            size_t base = ((size_t)n * LL + kv0 + r) * 3072 + h * 64 + c4;
            float4 kv = *reinterpret_cast<const float4*>(g_qkv + base + 1024);
            sK[r][c4 + 0] = __float2bfloat16(kv.x);
            sK[r][c4 + 1] = __float2bfloat16(kv.y);
            sK[r][c4 + 2] = __float2bfloat16(kv.z);
            sK[r][c4 + 3] = __float2bfloat16(kv.w);
            float4 vv = *reinterpret_cast<const float4*>(g_qkv + base + 2048);
            sVt[c4 + 0][r] = __float2bfloat16(vv.x);
            sVt[c4 + 1][r] = __float2bfloat16(vv.y);
            sVt[c4 + 2][r] = __float2bfloat16(vv.z);
            sVt[c4 + 3][r] = __float2bfloat16(vv.w);
        }
        __syncthreads();

        float s[16][4];
        #pragma unroll
        for (int j = 0; j < 16; j++) {
            s[j][0] = s[j][1] = s[j][2] = s[j][3] = 0.f;
            #pragma unroll
            for (int tt = 0; tt < 4; tt++) {
                unsigned b0 = *reinterpret_cast<unsigned*>(&sK[j*8 + g][tt*16 + 2*tg    ]);
                unsigned b1 = *reinterpret_cast<unsigned*>(&sK[j*8 + g][tt*16 + 2*tg + 8]);
                mma_bf16(s[j], aQ[tt], b0, b1);
            }
        }

        const unsigned* mr0 = mask + (mrow + g)     * (size_t)LL + kv0;
        const unsigned* mr1 = mask + (mrow + g + 8) * (size_t)LL + kv0;
        #pragma unroll
        for (int j = 0; j < 16; j++) {
            int col = j * 8 + 2 * tg;
            uint2 p0 = *reinterpret_cast<const uint2*>(mr0 + col);
            uint2 p1 = *reinterpret_cast<const uint2*>(mr1 + col);
            s[j][0] = p0.x ? 0.f : __expf(s[j][0]);
            s[j][1] = p0.y ? 0.f : __expf(s[j][1]);
            s[j][2] = p1.x ? 0.f : __expf(s[j][2]);
            s[j][3] = p1.y ? 0.f : __expf(s[j][3]);
            l0 += s[j][0] + s[j][1];
            l1 += s[j][2] + s[j][3];
        }

        #pragma unroll
        for (int tt = 0; tt < 8; tt++) {
            unsigned pa[4];
            pa[0] = pack_bf16(s[2*tt    ][0], s[2*tt    ][1]);
            pa[1] = pack_bf16(s[2*tt    ][2], s[2*tt    ][3]);
            pa[2] = pack_bf16(s[2*tt + 1][0], s[2*tt + 1][1]);
            pa[3] = pack_bf16(s[2*tt + 1][2], s[2*tt + 1][3]);
            #pragma unroll
            for (int nj = 0; nj < 8; nj++) {
                unsigned b0 = *reinterpret_cast<unsigned*>(&sVt[nj*8 + g][tt*16 + 2*tg    ]);
                unsigned b1 = *reinterpret_cast<unsigned*>(&sVt[nj*8 + g][tt*16 + 2*tg + 8]);
                mma_bf16(O[nj], pa, b0, b1);
            }
        }
    }

    l0 += __shfl_xor_sync(0xFFFFFFFFu, l0, 1);
    l0 += __shfl_xor_sync(0xFFFFFFFFu, l0, 2);
    l1 += __shfl_xor_sync(0xFFFFFFFFu, l1, 1);
    l1 += __shfl_xor_sync(0xFFFFFFFFu, l1, 2);
    float r0 = 1.f / l0, r1 = 1.f / l1;
    size_t orow = qrow0 + w * 16 + g;
    #pragma unroll
    for (int nj = 0; nj < 8; nj++) {
        int col = h * 64 + nj * 8 + 2 * tg;
        *reinterpret_cast<unsigned*>(g_attnb + orow * EN + col) =
            pack_bf16(O[nj][0] * r0, O[nj][1] * r0);
        *reinterpret_cast<unsigned*>(g_attnb + (orow + 8) * EN + col) =
            pack_bf16(O[nj][2] * r1, O[nj][3] * r1);
    }
}

// ---------------- launch -----------------------------------------------------
extern "C" void kernel_launch(void* const* d_in, const int* in_sizes, int n_in,
                              void* d_out, int out_size) {
    const float* x     = (const float*)d_in[0];
    const unsigned* mask = (const unsigned*)d_in[1];
    const float* ln1_s = (const float*)d_in[2];
    const float* ln1_b = (const float*)d_in[3];
    const float* Wqkv  = (const float*)d_in[4];
    const float* bqkv  = (const float*)d_in[5];
    const float* Wo    = (const float*)d_in[6];
    const float* bo    = (const float*)d_in[7];
    const float* ln2_s = (const float*)d_in[8];
    const float* ln2_b = (const float*)d_in[9];
    const float* lnf_s = (const float*)d_in[10];
    const float* lnf_b = (const float*)d_in[11];
    const float* W1    = (const float*)d_in[12];
    const float* b1    = (const float*)d_in[13];
    const float* W2    = (const float*)d_in[14];
    const float* b2    = (const float*)d_in[15];
    float* out = (float*)d_out;

    __nv_bfloat16 *p_hb, *p_attnb, *p_Wqkvt, *p_Wot;
    float *p_qkv, *p_x1, *p_h2, *p_ff, *p_W1t, *p_W2t;
    cudaGetSymbolAddress((void**)&p_hb,    g_hb);
    cudaGetSymbolAddress((void**)&p_qkv,   g_qkv);
    cudaGetSymbolAddress((void**)&p_attnb, g_attnb);
    cudaGetSymbolAddress((void**)&p_x1,    g_x1);
    cudaGetSymbolAddress((void**)&p_h2,    g_h2);
    cudaGetSymbolAddress((void**)&p_ff,    g_ff);
    cudaGetSymbolAddress((void**)&p_Wqkvt, g_Wqkvt);
    cudaGetSymbolAddress((void**)&p_Wot,   g_Wot);
    cudaGetSymbolAddress((void**)&p_W1t,   g_W1t);
    cudaGetSymbolAddress((void**)&p_W2t,   g_W2t);

    cudaFuncSetAttribute(gemm3_k<EPI_BIAS, __nv_bfloat16>, cudaFuncAttributeMaxDynamicSharedMemorySize, GEMM_SMEM);
    cudaFuncSetAttribute(gemm3_k<EPI_RES,  __nv_bfloat16>, cudaFuncAttributeMaxDynamicSharedMemorySize, GEMM_SMEM);
    cudaFuncSetAttribute(gemm3_k<EPI_GELU, float>,         cudaFuncAttributeMaxDynamicSharedMemorySize, GEMM_SMEM);
    cudaFuncSetAttribute(gemm3_k<EPI_RES,  float>,         cudaFuncAttributeMaxDynamicSharedMemorySize, GEMM_SMEM);

    dim3 tb(32, 8);
    // weight pre-pass: transpose (+convert)
    transT_bf16_k<<<dim3(3*EN/32, EN/32), tb>>>(Wqkv, p_Wqkvt, EN, 3*EN);
    transT_bf16_k<<<dim3(EN/32,   EN/32), tb>>>(Wo,   p_Wot,   EN, EN);
    transT_f32_k <<<dim3(DFFN/32, EN/32), tb>>>(W1,   p_W1t,   EN, DFFN);
    transT_f32_k <<<dim3(EN/32, DFFN/32), tb>>>(W2,   p_W2t,   DFFN, EN);

    // 1. h = LN1(x) -> bf16
    ln1_k<<<ROWS, 256>>>(x, ln1_s, ln1_b, p_hb);
    // 2. qkv = h @ Wqkv + bqkv (bf16)
    gemm3_k<EPI_BIAS, __nv_bfloat16><<<dim3(3*EN/128, ROWS/128), 128, GEMM_SMEM>>>(
        ROWS, 3*EN, EN, p_hb, p_Wqkvt, bqkv, nullptr, p_qkv);
    // 3. attention -> bf16
    attn_k<<<dim3(LL/64, NB*HHH), 128>>>(mask);
    // 4. x1 = x + attn @ Wo + bo (bf16)
    gemm3_k<EPI_RES, __nv_bfloat16><<<dim3(EN/128, ROWS/128), 128, GEMM_SMEM>>>(
        ROWS, EN, EN, p_attnb, p_Wot, bo, x, p_x1);
    // 5. h2 = LNf(LN2(x1)) (rna)
    ln2f_k<<<ROWS, 256>>>(p_x1, ln2_s, ln2_b, lnf_s, lnf_b, p_h2);
    // 6. ff = gelu(h2 @ W1 + b1) (tf32, rna out)
    gemm3_k<EPI_GELU, float><<<dim3(DFFN/128, ROWS/128), 128, GEMM_SMEM>>>(
        ROWS, DFFN, EN, p_h2, p_W1t, b1, nullptr, p_ff);
    // 7. out = x1 + ff @ W2 + b2 (tf32)
    gemm3_k<EPI_RES, float><<<dim3(EN/128, ROWS/128), 128, GEMM_SMEM>>>(
        ROWS, EN, DFFN, p_ff, p_W2t, b2, p_x1, out);
}

// round 6
// speedup vs baseline: 1.5648x; 1.2361x over previous
#include <cuda_runtime.h>
#include <cuda_fp16.h>
#include <cuda_bf16.h>
#include <cstdint>

#define EN   1024
#define DFFN 4096
#define NB   2
#define LL   2048
#define HHH  16
#define ROWS (NB*LL)   // 4096

// ---------------- scratch (device globals; no allocation allowed) ----------
__device__ __half g_hh   [ROWS*EN];      // LN1 out (A of QKV)
__device__ float  g_qkv  [ROWS*3*EN];    // QKV projection (fp32, read by attn)
__device__ __half g_attnh[ROWS*EN];      // attn out (A of Wo)
__device__ float  g_x1   [ROWS*EN];      // x + attn@Wo + bo (fp32 trunk)
__device__ __half g_h2   [ROWS*EN];      // LNf(LN2(x1)) (A of FF1)
__device__ __half g_ff   [ROWS*DFFN];    // gelu(h2@W1+b1) (A of FF2)
// transposed fp16 weights (refreshed every launch)
__device__ __half g_Wqkvt[3*EN*EN];      // [3E][E]
__device__ __half g_Wot  [EN*EN];        // [E][E]
__device__ __half g_W1t  [DFFN*EN];      // [DFF][E]
__device__ __half g_W2t  [EN*DFFN];      // [E][DFF]

// ---------------- helpers ---------------------------------------------------
__device__ __forceinline__ unsigned pack_bf16(float lo, float hi) {
    __nv_bfloat162 p = __floats2bfloat162_rn(lo, hi);
    return *reinterpret_cast<unsigned*>(&p);
}
__device__ __forceinline__ unsigned pack_f16(float lo, float hi) {
    __half2 p = __floats2half2_rn(lo, hi);
    return *reinterpret_cast<unsigned*>(&p);
}
__device__ __forceinline__ void mma_f16(float* c, const unsigned* a, unsigned b0, unsigned b1) {
    asm volatile(
        "mma.sync.aligned.m16n8k16.row.col.f32.f16.f16.f32 "
        "{%0,%1,%2,%3},{%4,%5,%6,%7},{%8,%9},{%0,%1,%2,%3};"
        : "+f"(c[0]), "+f"(c[1]), "+f"(c[2]), "+f"(c[3])
        : "r"(a[0]), "r"(a[1]), "r"(a[2]), "r"(a[3]), "r"(b0), "r"(b1));
}
__device__ __forceinline__ void mma_bf16(float* c, const unsigned* a, unsigned b0, unsigned b1) {
    asm volatile(
        "mma.sync.aligned.m16n8k16.row.col.f32.bf16.bf16.f32 "
        "{%0,%1,%2,%3},{%4,%5,%6,%7},{%8,%9},{%0,%1,%2,%3};"
        : "+f"(c[0]), "+f"(c[1]), "+f"(c[2]), "+f"(c[3])
        : "r"(a[0]), "r"(a[1]), "r"(a[2]), "r"(a[3]), "r"(b0), "r"(b1));
}
__device__ __forceinline__ void cpa16(unsigned dst, const void* src) {
    asm volatile("cp.async.cg.shared.global [%0], [%1], 16;\n" :: "r"(dst), "l"(src));
}
#define CP_COMMIT() asm volatile("cp.async.commit_group;\n" ::)
#define CP_WAIT0()  asm volatile("cp.async.wait_group 0;\n" ::)

__device__ __forceinline__ void blockReduce2(float& a, float& b) {
    __shared__ float sm[16];
    #pragma unroll
    for (int o = 16; o; o >>= 1) {
        a += __shfl_xor_sync(0xFFFFFFFFu, a, o);
        b += __shfl_xor_sync(0xFFFFFFFFu, b, o);
    }
    int w = threadIdx.x >> 5, lane = threadIdx.x & 31;
    __syncthreads();
    if (lane == 0) { sm[w] = a; sm[8 + w] = b; }
    __syncthreads();
    a = 0.f; b = 0.f;
    #pragma unroll
    for (int i = 0; i < 8; i++) { a += sm[i]; b += sm[8 + i]; }
}

// ---------------- weight pre-pass: transpose + fp16 --------------------------
// out[n][k] = f16(in[k][n]); grid (N/32, K/32), block (32,8)
__global__ __launch_bounds__(256) void transT_f16_k(const float* __restrict__ in,
                                                    __half* __restrict__ out,
                                                    int K, int N) {
    __shared__ float tile[32][33];
    int k0 = blockIdx.y * 32, n0 = blockIdx.x * 32;
    int tx = threadIdx.x, ty = threadIdx.y;
    #pragma unroll
    for (int i = 0; i < 32; i += 8)
        tile[ty + i][tx] = in[(size_t)(k0 + ty + i) * N + n0 + tx];
    __syncthreads();
    #pragma unroll
    for (int i = 0; i < 32; i += 8)
        out[(size_t)(n0 + ty + i) * K + k0 + tx] = __float2half(tile[tx][ty + i]);
}

// ---------------- LN1: writes fp16 -------------------------------------------
__global__ __launch_bounds__(256) void ln1_k(const float* __restrict__ x,
                                             const float* __restrict__ s,
                                             const float* __restrict__ b,
                                             __half* __restrict__ out) {
    int row = blockIdx.x, t = threadIdx.x;
    float4 v = reinterpret_cast<const float4*>(x + (size_t)row * EN)[t];
    float sum = v.x + v.y + v.z + v.w;
    float sq  = v.x*v.x + v.y*v.y + v.z*v.z + v.w*v.w;
    blockReduce2(sum, sq);
    float mu = sum * (1.f / EN);
    float rs = rsqrtf(sq * (1.f / EN) - mu * mu + 1e-5f);
    float4 sv = reinterpret_cast<const float4*>(s)[t];
    float4 bv = reinterpret_cast<const float4*>(b)[t];
    uint2 pk;
    pk.x = pack_f16((v.x - mu) * rs * sv.x + bv.x, (v.y - mu) * rs * sv.y + bv.y);
    pk.y = pack_f16((v.z - mu) * rs * sv.z + bv.z, (v.w - mu) * rs * sv.w + bv.w);
    reinterpret_cast<uint2*>(out + (size_t)row * EN)[t] = pk;
}

// ---------------- LN2 then LNf fused: writes fp16 ----------------------------
__global__ __launch_bounds__(256) void ln2f_k(const float* __restrict__ x,
                                              const float* __restrict__ s2,
                                              const float* __restrict__ b2,
                                              const float* __restrict__ sf,
                                              const float* __restrict__ bf,
                                              __half* __restrict__ out) {
    int row = blockIdx.x, t = threadIdx.x;
    float4 v = reinterpret_cast<const float4*>(x + (size_t)row * EN)[t];
    float sum = v.x + v.y + v.z + v.w;
    float sq  = v.x*v.x + v.y*v.y + v.z*v.z + v.w*v.w;
    blockReduce2(sum, sq);
    float mu = sum * (1.f / EN);
    float rs = rsqrtf(sq * (1.f / EN) - mu * mu + 1e-5f);
    float4 sv = reinterpret_cast<const float4*>(s2)[t];
    float4 bv = reinterpret_cast<const float4*>(b2)[t];
    float4 y;
    y.x = (v.x - mu) * rs * sv.x + bv.x;
    y.y = (v.y - mu) * rs * sv.y + bv.y;
    y.z = (v.z - mu) * rs * sv.z + bv.z;
    y.w = (v.w - mu) * rs * sv.w + bv.w;
    float sum2 = y.x + y.y + y.z + y.w;
    float sq2  = y.x*y.x + y.y*y.y + y.z*y.z + y.w*y.w;
    blockReduce2(sum2, sq2);
    float mu2 = sum2 * (1.f / EN);
    float rs2 = rsqrtf(sq2 * (1.f / EN) - mu2 * mu2 + 1e-5f);
    float4 fv = reinterpret_cast<const float4*>(sf)[t];
    float4 gv = reinterpret_cast<const float4*>(bf)[t];
    uint2 pk;
    pk.x = pack_f16((y.x - mu2) * rs2 * fv.x + gv.x, (y.y - mu2) * rs2 * fv.y + gv.y);
    pk.y = pack_f16((y.z - mu2) * rs2 * fv.z + gv.z, (y.w - mu2) * rs2 * fv.w + gv.w);
    reinterpret_cast<uint2*>(out + (size_t)row * EN)[t] = pk;
}

// ---------------- fp16 GEMM: C = epi(A@Bt^T + bias [+res]) -------------------
// A [M][K] fp16 row-major, Bt [N][K] fp16 row-major. BM=BN=128, K chunk = 64
// elems (128B/row). 128 threads, 4 warps 2x2, warp tile 64x64. pi-permuted
// k-groups: every fragment load is one LDS.128. Stride 48 words: conflict-free.
#define EPI_BIAS 0
#define EPI_GELU 1
#define EPI_RES  2

#define STG_WORDS (2*128*48)        // A-half + B-half
#define GEMM_SMEM (2*STG_WORDS*4)   // 98304 bytes, 2 stages

template <int EPI, typename TO>
__global__ __launch_bounds__(128, 2) void gemm4_k(int M, int N, int K,
                                                  const __half* __restrict__ A,
                                                  const __half* __restrict__ Bt,
                                                  const float* __restrict__ bias,
                                                  const float* __restrict__ res,
                                                  TO* __restrict__ C) {
    extern __shared__ float smem[];
    constexpr int BKE = 64;               // K elems per tile chunk
    int bm = blockIdx.y * 128, bn = blockIdx.x * 128;
    int t = threadIdx.x, wid = t >> 5, lane = t & 31;
    int g = lane >> 2, tg = lane & 3;
    int wr = (wid & 1) * 64;
    int wc = (wid >> 1) * 64;

    float c[4][8][4];
    #pragma unroll
    for (int mi = 0; mi < 4; mi++)
        #pragma unroll
        for (int nj = 0; nj < 8; nj++)
            #pragma unroll
            for (int q = 0; q < 4; q++) c[mi][nj][q] = 0.f;

    const __half* Ab = A  + (size_t)bm * K;
    const __half* Bb = Bt + (size_t)bn * K;
    int r8 = t >> 3, c8 = t & 7;

    auto prefetch = [&](int kt, int s) {
        float* dA = smem + s * STG_WORDS;
        float* dB = dA + 128 * 48;
        size_t kofs = (size_t)kt * BKE + c8 * 8;
        unsigned da = (unsigned)__cvta_generic_to_shared(dA + r8 * 48 + c8 * 4);
        unsigned db = (unsigned)__cvta_generic_to_shared(dB + r8 * 48 + c8 * 4);
        #pragma unroll
        for (int i = 0; i < 8; i++) {
            cpa16(da + i * 16 * 48 * 4, Ab + (size_t)(r8 + i * 16) * K + kofs);
            cpa16(db + i * 16 * 48 * 4, Bb + (size_t)(r8 + i * 16) * K + kofs);
        }
    };

    int Tn = K / BKE;
    prefetch(0, 0);
    CP_COMMIT();

    for (int kt = 0; kt < Tn; kt++) {
        int s = kt & 1;
        CP_WAIT0();
        __syncthreads();
        if (kt + 1 < Tn) { prefetch(kt + 1, s ^ 1); CP_COMMIT(); }

        const float* cA = smem + s * STG_WORDS;
        const float* cB = cA + 128 * 48;
        #pragma unroll
        for (int u = 0; u < 2; u++) {
            uint4 aF[8], bF[8];
            #pragma unroll
            for (int i = 0; i < 8; i++) {
                int r = wr + (i >> 1) * 16 + g + (i & 1) * 8;
                aF[i] = *reinterpret_cast<const uint4*>(cA + r * 48 + u * 16 + tg * 4);
            }
            #pragma unroll
            for (int nj = 0; nj < 8; nj++) {
                int cc = wc + nj * 8 + g;
                bF[nj] = *reinterpret_cast<const uint4*>(cB + cc * 48 + u * 16 + tg * 4);
            }
            #pragma unroll
            for (int mi = 0; mi < 4; mi++) {
                unsigned ae[4] = {aF[2*mi].x, aF[2*mi+1].x, aF[2*mi].y, aF[2*mi+1].y};
                unsigned ao[4] = {aF[2*mi].z, aF[2*mi+1].z, aF[2*mi].w, aF[2*mi+1].w};
                #pragma unroll
                for (int nj = 0; nj < 8; nj++) {
                    mma_f16(c[mi][nj], ae, bF[nj].x, bF[nj].y);
                    mma_f16(c[mi][nj], ao, bF[nj].z, bF[nj].w);
                }
            }
        }
    }

    #pragma unroll
    for (int mi = 0; mi < 4; mi++) {
        #pragma unroll
        for (int nj = 0; nj < 8; nj++) {
            int row = bm + wr + mi * 16 + g;
            int col = bn + wc + nj * 8 + tg * 2;
            float b0 = bias[col], b1 = bias[col + 1];
            float v0 = c[mi][nj][0] + b0, v1 = c[mi][nj][1] + b1;
            float v2 = c[mi][nj][2] + b0, v3 = c[mi][nj][3] + b1;
            if (EPI == EPI_GELU) {
                v0 = 0.5f * v0 * (1.f + erff(v0 * 0.70710678118f));
                v1 = 0.5f * v1 * (1.f + erff(v1 * 0.70710678118f));
                v2 = 0.5f * v2 * (1.f + erff(v2 * 0.70710678118f));
                v3 = 0.5f * v3 * (1.f + erff(v3 * 0.70710678118f));
            }
            if (EPI == EPI_RES) {
                float2 r0 = *reinterpret_cast<const float2*>(res + (size_t)row * N + col);
                float2 r1 = *reinterpret_cast<const float2*>(res + (size_t)(row + 8) * N + col);
                v0 += r0.x; v1 += r0.y; v2 += r1.x; v3 += r1.y;
            }
            if (sizeof(TO) == 4) {
                float* Cf = (float*)C;
                *reinterpret_cast<float2*>(Cf + (size_t)row * N + col)       = make_float2(v0, v1);
                *reinterpret_cast<float2*>(Cf + (size_t)(row + 8) * N + col) = make_float2(v2, v3);
            } else {
                __half* Ch = (__half*)C;
                *reinterpret_cast<unsigned*>(Ch + (size_t)row * N + col)       = pack_f16(v0, v1);
                *reinterpret_cast<unsigned*>(Ch + (size_t)(row + 8) * N + col) = pack_f16(v2, v3);
            }
        }
    }
}

// ---------------- bf16 flash attention (R4 structure, fp16 output) -----------
__global__ __launch_bounds__(128) void attn_k(const unsigned* __restrict__ mask) {
    __shared__ __nv_bfloat16 sQ [64][72];
    __shared__ __nv_bfloat16 sK [128][72];
    __shared__ __nv_bfloat16 sVt[64][136];

    int t = threadIdx.x, w = t >> 5, lane = t & 31;
    int g = lane >> 2, tg = lane & 3;
    int qt = blockIdx.x, nh = blockIdx.y;
    int n = nh >> 4, h = nh & 15;
    size_t qrow0 = (size_t)n * LL + (size_t)qt * 64;

    #pragma unroll
    for (int i = 0; i < 8; i++) {
        int id = t + i * 128;
        int r = id >> 4, c4 = (id & 15) * 4;
        float4 v = *reinterpret_cast<const float4*>(g_qkv + (qrow0 + r) * 3072 + h * 64 + c4);
        sQ[r][c4 + 0] = __float2bfloat16(v.x * 0.125f);
        sQ[r][c4 + 1] = __float2bfloat16(v.y * 0.125f);
        sQ[r][c4 + 2] = __float2bfloat16(v.z * 0.125f);
        sQ[r][c4 + 3] = __float2bfloat16(v.w * 0.125f);
    }
    __syncthreads();

    unsigned aQ[4][4];
    #pragma unroll
    for (int tt = 0; tt < 4; tt++) {
        aQ[tt][0] = *reinterpret_cast<unsigned*>(&sQ[w*16 + g    ][tt*16 + 2*tg    ]);
        aQ[tt][1] = *reinterpret_cast<unsigned*>(&sQ[w*16 + g + 8][tt*16 + 2*tg    ]);
        aQ[tt][2] = *reinterpret_cast<unsigned*>(&sQ[w*16 + g    ][tt*16 + 2*tg + 8]);
        aQ[tt][3] = *reinterpret_cast<unsigned*>(&sQ[w*16 + g + 8][tt*16 + 2*tg + 8]);
    }

    float O[8][4];
    #pragma unroll
    for (int nj = 0; nj < 8; nj++)
        #pragma unroll
        for (int q = 0; q < 4; q++) O[nj][q] = 0.f;
    float l0 = 0.f, l1 = 0.f;

    size_t mrow = (size_t)nh * LL + (size_t)qt * 64 + w * 16;

    for (int kv0 = 0; kv0 < LL; kv0 += 128) {
        __syncthreads();
        #pragma unroll
        for (int i = 0; i < 16; i++) {
            int id = t + i * 128;
            int r = id >> 4, c4 = (id & 15) * 4;
            size_t base = ((size_t)n * LL + kv0 + r) * 3072 + h * 64 + c4;
            float4 kv = *reinterpret_cast<const float4*>(g_qkv + base + 1024);
            sK[r][c4 + 0] = __float2bfloat16(kv.x);
            sK[r][c4 + 1] = __float2bfloat16(kv.y);
            sK[r][c4 + 2] = __float2bfloat16(kv.z);
            sK[r][c4 + 3] = __float2bfloat16(kv.w);
            float4 vv = *reinterpret_cast<const float4*>(g_qkv + base + 2048);
            sVt[c4 + 0][r] = __float2bfloat16(vv.x);
            sVt[c4 + 1][r] = __float2bfloat16(vv.y);
            sVt[c4 + 2][r] = __float2bfloat16(vv.z);
            sVt[c4 + 3][r] = __float2bfloat16(vv.w);
        }
        __syncthreads();

        float s[16][4];
        #pragma unroll
        for (int j = 0; j < 16; j++) {
            s[j][0] = s[j][1] = s[j][2] = s[j][3] = 0.f;
            #pragma unroll
            for (int tt = 0; tt < 4; tt++) {
                unsigned b0 = *reinterpret_cast<unsigned*>(&sK[j*8 + g][tt*16 + 2*tg    ]);
                unsigned b1 = *reinterpret_cast<unsigned*>(&sK[j*8 + g][tt*16 + 2*tg + 8]);
                mma_bf16(s[j], aQ[tt], b0, b1);
            }
        }

        const unsigned* mr0 = mask + (mrow + g)     * (size_t)LL + kv0;
        const unsigned* mr1 = mask + (mrow + g + 8) * (size_t)LL + kv0;
        #pragma unroll
        for (int j = 0; j < 16; j++) {
            int col = j * 8 + 2 * tg;
            uint2 p0 = *reinterpret_cast<const uint2*>(mr0 + col);
            uint2 p1 = *reinterpret_cast<const uint2*>(mr1 + col);
            s[j][0] = p0.x ? 0.f : __expf(s[j][0]);
            s[j][1] = p0.y ? 0.f : __expf(s[j][1]);
            s[j][2] = p1.x ? 0.f : __expf(s[j][2]);
            s[j][3] = p1.y ? 0.f : __expf(s[j][3]);
            l0 += s[j][0] + s[j][1];
            l1 += s[j][2] + s[j][3];
        }

        #pragma unroll
        for (int tt = 0; tt < 8; tt++) {
            unsigned pa[4];
            pa[0] = pack_bf16(s[2*tt    ][0], s[2*tt    ][1]);
            pa[1] = pack_bf16(s[2*tt    ][2], s[2*tt    ][3]);
            pa[2] = pack_bf16(s[2*tt + 1][0], s[2*tt + 1][1]);
            pa[3] = pack_bf16(s[2*tt + 1][2], s[2*tt + 1][3]);
            #pragma unroll
            for (int nj = 0; nj < 8; nj++) {
                unsigned b0 = *reinterpret_cast<unsigned*>(&sVt[nj*8 + g][tt*16 + 2*tg    ]);
                unsigned b1 = *reinterpret_cast<unsigned*>(&sVt[nj*8 + g][tt*16 + 2*tg + 8]);
                mma_bf16(O[nj], pa, b0, b1);
            }
        }
    }

    l0 += __shfl_xor_sync(0xFFFFFFFFu, l0, 1);
    l0 += __shfl_xor_sync(0xFFFFFFFFu, l0, 2);
    l1 += __shfl_xor_sync(0xFFFFFFFFu, l1, 1);
    l1 += __shfl_xor_sync(0xFFFFFFFFu, l1, 2);
    float r0 = 1.f / l0, r1 = 1.f / l1;
    size_t orow = qrow0 + w * 16 + g;
    #pragma unroll
    for (int nj = 0; nj < 8; nj++) {
        int col = h * 64 + nj * 8 + 2 * tg;
        *reinterpret_cast<unsigned*>(g_attnh + orow * EN + col) =
            pack_f16(O[nj][0] * r0, O[nj][1] * r0);
        *reinterpret_cast<unsigned*>(g_attnh + (orow + 8) * EN + col) =
            pack_f16(O[nj][2] * r1, O[nj][3] * r1);
    }
}

// ---------------- launch -----------------------------------------------------
extern "C" void kernel_launch(void* const* d_in, const int* in_sizes, int n_in,
                              void* d_out, int out_size) {
    const float* x     = (const float*)d_in[0];
    const unsigned* mask = (const unsigned*)d_in[1];
    const float* ln1_s = (const float*)d_in[2];
    const float* ln1_b = (const float*)d_in[3];
    const float* Wqkv  = (const float*)d_in[4];
    const float* bqkv  = (const float*)d_in[5];
    const float* Wo    = (const float*)d_in[6];
    const float* bo    = (const float*)d_in[7];
    const float* ln2_s = (const float*)d_in[8];
    const float* ln2_b = (const float*)d_in[9];
    const float* lnf_s = (const float*)d_in[10];
    const float* lnf_b = (const float*)d_in[11];
    const float* W1    = (const float*)d_in[12];
    const float* b1    = (const float*)d_in[13];
    const float* W2    = (const float*)d_in[14];
    const float* b2    = (const float*)d_in[15];
    float* out = (float*)d_out;

    __half *p_hh, *p_attnh, *p_h2, *p_ff, *p_Wqkvt, *p_Wot, *p_W1t, *p_W2t;
    float *p_qkv, *p_x1;
    cudaGetSymbolAddress((void**)&p_hh,    g_hh);
    cudaGetSymbolAddress((void**)&p_qkv,   g_qkv);
    cudaGetSymbolAddress((void**)&p_attnh, g_attnh);
    cudaGetSymbolAddress((void**)&p_x1,    g_x1);
    cudaGetSymbolAddress((void**)&p_h2,    g_h2);
    cudaGetSymbolAddress((void**)&p_ff,    g_ff);
    cudaGetSymbolAddress((void**)&p_Wqkvt, g_Wqkvt);
    cudaGetSymbolAddress((void**)&p_Wot,   g_Wot);
    cudaGetSymbolAddress((void**)&p_W1t,   g_W1t);
    cudaGetSymbolAddress((void**)&p_W2t,   g_W2t);

    cudaFuncSetAttribute(gemm4_k<EPI_BIAS, float>,  cudaFuncAttributeMaxDynamicSharedMemorySize, GEMM_SMEM);
    cudaFuncSetAttribute(gemm4_k<EPI_RES,  float>,  cudaFuncAttributeMaxDynamicSharedMemorySize, GEMM_SMEM);
    cudaFuncSetAttribute(gemm4_k<EPI_GELU, __half>, cudaFuncAttributeMaxDynamicSharedMemorySize, GEMM_SMEM);

    dim3 tb(32, 8);
    // weight pre-pass: transpose + fp16
    transT_f16_k<<<dim3(3*EN/32, EN/32), tb>>>(Wqkv, p_Wqkvt, EN, 3*EN);
    transT_f16_k<<<dim3(EN/32,   EN/32), tb>>>(Wo,   p_Wot,   EN, EN);
    transT_f16_k<<<dim3(DFFN/32, EN/32), tb>>>(W1,   p_W1t,   EN, DFFN);
    transT_f16_k<<<dim3(EN/32, DFFN/32), tb>>>(W2,   p_W2t,   DFFN, EN);

    // 1. h = LN1(x) -> fp16
    ln1_k<<<ROWS, 256>>>(x, ln1_s, ln1_b, p_hh);
    // 2. qkv = h @ Wqkv + bqkv (fp16 -> fp32)
    gemm4_k<EPI_BIAS, float><<<dim3(3*EN/128, ROWS/128), 128, GEMM_SMEM>>>(
        ROWS, 3*EN, EN, p_hh, p_Wqkvt, bqkv, nullptr, p_qkv);
    // 3. attention -> fp16
    attn_k<<<dim3(LL/64, NB*HHH), 128>>>(mask);
    // 4. x1 = x + attn @ Wo + bo (fp16 -> fp32)
    gemm4_k<EPI_RES, float><<<dim3(EN/128, ROWS/128), 128, GEMM_SMEM>>>(
        ROWS, EN, EN, p_attnh, p_Wot, bo, x, p_x1);
    // 5. h2 = LNf(LN2(x1)) -> fp16
    ln2f_k<<<ROWS, 256>>>(p_x1, ln2_s, ln2_b, lnf_s, lnf_b, p_h2);
    // 6. ff = gelu(h2 @ W1 + b1) (fp16 -> fp16)
    gemm4_k<EPI_GELU, __half><<<dim3(DFFN/128, ROWS/128), 128, GEMM_SMEM>>>(
        ROWS, DFFN, EN, p_h2, p_W1t, b1, nullptr, p_ff);
    // 7. out = x1 + ff @ W2 + b2 (fp16 -> fp32)
    gemm4_k<EPI_RES, float><<<dim3(EN/128, ROWS/128), 128, GEMM_SMEM>>>(
        ROWS, EN, DFFN, p_ff, p_W2t, b2, p_x1, out);
}

// round 7
// speedup vs baseline: 1.6716x; 1.0683x over previous
#include <cuda_runtime.h>
#include <cuda_fp16.h>
#include <cstdint>

#define EN   1024
#define DFFN 4096
#define NB   2
#define LL   2048
#define HHH  16
#define ROWS (NB*LL)   // 4096

// ---------------- scratch (device globals; no allocation allowed) ----------
__device__ __half g_hh   [ROWS*EN];      // LN1 out (A of QKV)
__device__ __half g_qkvh [ROWS*3*EN];    // QKV projection (fp16; q pre-scaled)
__device__ __half g_attnh[ROWS*EN];      // attn out (A of Wo)
__device__ float  g_x1   [ROWS*EN];      // x + attn@Wo + bo (fp32 trunk)
__device__ __half g_h2   [ROWS*EN];      // LNf(LN2(x1)) (A of FF1)
__device__ __half g_ff   [ROWS*DFFN];    // gelu(h2@W1+b1) (A of FF2)
__device__ float  g_bqkv [3*EN];         // bqkv with q-part scaled by 0.125
// transposed fp16 weights (refreshed every launch)
__device__ __half g_Wqkvt[3*EN*EN];      // [3E][E] (q-rows pre-scaled 0.125)
__device__ __half g_Wot  [EN*EN];
__device__ __half g_W1t  [DFFN*EN];
__device__ __half g_W2t  [EN*DFFN];

// ---------------- helpers ---------------------------------------------------
__device__ __forceinline__ unsigned pack_f16(float lo, float hi) {
    __half2 p = __floats2half2_rn(lo, hi);
    return *reinterpret_cast<unsigned*>(&p);
}
__device__ __forceinline__ void mma_f16(float* c, const unsigned* a, unsigned b0, unsigned b1) {
    asm volatile(
        "mma.sync.aligned.m16n8k16.row.col.f32.f16.f16.f32 "
        "{%0,%1,%2,%3},{%4,%5,%6,%7},{%8,%9},{%0,%1,%2,%3};"
        : "+f"(c[0]), "+f"(c[1]), "+f"(c[2]), "+f"(c[3])
        : "r"(a[0]), "r"(a[1]), "r"(a[2]), "r"(a[3]), "r"(b0), "r"(b1));
}
__device__ __forceinline__ void cpa16(unsigned dst, const void* src) {
    asm volatile("cp.async.cg.shared.global [%0], [%1], 16;\n" :: "r"(dst), "l"(src));
}
#define CP_COMMIT() asm volatile("cp.async.commit_group;\n" ::)
#define CP_WAIT0()  asm volatile("cp.async.wait_group 0;\n" ::)
#define CP_WAIT1()  asm volatile("cp.async.wait_group 1;\n" ::)

__device__ __forceinline__ uint32_t smem_u32(const void* p) {
    uint32_t a;
    asm("{ .reg .u64 t; cvta.to.shared.u64 t, %1; cvt.u32.u64 %0, t; }" : "=r"(a) : "l"(p));
    return a;
}
__device__ __forceinline__ void ldsm_x4(unsigned* r, uint32_t addr) {
    asm volatile("ldmatrix.sync.aligned.m8n8.x4.shared.b16 {%0,%1,%2,%3}, [%4];"
        : "=r"(r[0]), "=r"(r[1]), "=r"(r[2]), "=r"(r[3]) : "r"(addr));
}
__device__ __forceinline__ void ldsm_x4_t(unsigned* r, uint32_t addr) {
    asm volatile("ldmatrix.sync.aligned.m8n8.x4.trans.shared.b16 {%0,%1,%2,%3}, [%4];"
        : "=r"(r[0]), "=r"(r[1]), "=r"(r[2]), "=r"(r[3]) : "r"(addr));
}

__device__ __forceinline__ void blockReduce2(float& a, float& b) {
    __shared__ float sm[16];
    #pragma unroll
    for (int o = 16; o; o >>= 1) {
        a += __shfl_xor_sync(0xFFFFFFFFu, a, o);
        b += __shfl_xor_sync(0xFFFFFFFFu, b, o);
    }
    int w = threadIdx.x >> 5, lane = threadIdx.x & 31;
    __syncthreads();
    if (lane == 0) { sm[w] = a; sm[8 + w] = b; }
    __syncthreads();
    a = 0.f; b = 0.f;
    #pragma unroll
    for (int i = 0; i < 8; i++) { a += sm[i]; b += sm[8 + i]; }
}

// ---------------- pre-pass kernels -------------------------------------------
// out[n][k] = f16(in[k][n] * (n < slim ? sc : 1))
__global__ __launch_bounds__(256) void transT_f16_k(const float* __restrict__ in,
                                                    __half* __restrict__ out,
                                                    int K, int N, int slim, float sc) {
    __shared__ float tile[32][33];
    int k0 = blockIdx.y * 32, n0 = blockIdx.x * 32;
    int tx = threadIdx.x, ty = threadIdx.y;
    #pragma unroll
    for (int i = 0; i < 32; i += 8)
        tile[ty + i][tx] = in[(size_t)(k0 + ty + i) * N + n0 + tx];
    __syncthreads();
    #pragma unroll
    for (int i = 0; i < 32; i += 8) {
        int n = n0 + ty + i;
        float v = tile[tx][ty + i];
        out[(size_t)n * K + k0 + tx] = __float2half(n < slim ? v * sc : v);
    }
}
__global__ __launch_bounds__(256) void scale_bias_k(const float* __restrict__ in,
                                                    float* __restrict__ out) {
    int i = blockIdx.x * 256 + threadIdx.x;
    out[i] = i < EN ? in[i] * 0.125f : in[i];
}

// ---------------- LN kernels -------------------------------------------------
__global__ __launch_bounds__(256) void ln1_k(const float* __restrict__ x,
                                             const float* __restrict__ s,
                                             const float* __restrict__ b,
                                             __half* __restrict__ out) {
    int row = blockIdx.x, t = threadIdx.x;
    float4 v = reinterpret_cast<const float4*>(x + (size_t)row * EN)[t];
    float sum = v.x + v.y + v.z + v.w;
    float sq  = v.x*v.x + v.y*v.y + v.z*v.z + v.w*v.w;
    blockReduce2(sum, sq);
    float mu = sum * (1.f / EN);
    float rs = rsqrtf(sq * (1.f / EN) - mu * mu + 1e-5f);
    float4 sv = reinterpret_cast<const float4*>(s)[t];
    float4 bv = reinterpret_cast<const float4*>(b)[t];
    uint2 pk;
    pk.x = pack_f16((v.x - mu) * rs * sv.x + bv.x, (v.y - mu) * rs * sv.y + bv.y);
    pk.y = pack_f16((v.z - mu) * rs * sv.z + bv.z, (v.w - mu) * rs * sv.w + bv.w);
    reinterpret_cast<uint2*>(out + (size_t)row * EN)[t] = pk;
}

__global__ __launch_bounds__(256) void ln2f_k(const float* __restrict__ x,
                                              const float* __restrict__ s2,
                                              const float* __restrict__ b2,
                                              const float* __restrict__ sf,
                                              const float* __restrict__ bf,
                                              __half* __restrict__ out) {
    int row = blockIdx.x, t = threadIdx.x;
    float4 v = reinterpret_cast<const float4*>(x + (size_t)row * EN)[t];
    float sum = v.x + v.y + v.z + v.w;
    float sq  = v.x*v.x + v.y*v.y + v.z*v.z + v.w*v.w;
    blockReduce2(sum, sq);
    float mu = sum * (1.f / EN);
    float rs = rsqrtf(sq * (1.f / EN) - mu * mu + 1e-5f);
    float4 sv = reinterpret_cast<const float4*>(s2)[t];
    float4 bv = reinterpret_cast<const float4*>(b2)[t];
    float4 y;
    y.x = (v.x - mu) * rs * sv.x + bv.x;
    y.y = (v.y - mu) * rs * sv.y + bv.y;
    y.z = (v.z - mu) * rs * sv.z + bv.z;
    y.w = (v.w - mu) * rs * sv.w + bv.w;
    float sum2 = y.x + y.y + y.z + y.w;
    float sq2  = y.x*y.x + y.y*y.y + y.z*y.z + y.w*y.w;
    blockReduce2(sum2, sq2);
    float mu2 = sum2 * (1.f / EN);
    float rs2 = rsqrtf(sq2 * (1.f / EN) - mu2 * mu2 + 1e-5f);
    float4 fv = reinterpret_cast<const float4*>(sf)[t];
    float4 gv = reinterpret_cast<const float4*>(bf)[t];
    uint2 pk;
    pk.x = pack_f16((y.x - mu2) * rs2 * fv.x + gv.x, (y.y - mu2) * rs2 * fv.y + gv.y);
    pk.y = pack_f16((y.z - mu2) * rs2 * fv.z + gv.z, (y.w - mu2) * rs2 * fv.w + gv.w);
    reinterpret_cast<uint2*>(out + (size_t)row * EN)[t] = pk;
}

// ---------------- fp16 GEMM (unchanged structure from R6) --------------------
#define EPI_BIAS 0
#define EPI_GELU 1
#define EPI_RES  2

#define STG_WORDS (2*128*48)
#define GEMM_SMEM (2*STG_WORDS*4)

template <int EPI, typename TO>
__global__ __launch_bounds__(128, 2) void gemm4_k(int M, int N, int K,
                                                  const __half* __restrict__ A,
                                                  const __half* __restrict__ Bt,
                                                  const float* __restrict__ bias,
                                                  const float* __restrict__ res,
                                                  TO* __restrict__ C) {
    extern __shared__ float smem[];
    constexpr int BKE = 64;
    int bm = blockIdx.y * 128, bn = blockIdx.x * 128;
    int t = threadIdx.x, wid = t >> 5, lane = t & 31;
    int g = lane >> 2, tg = lane & 3;
    int wr = (wid & 1) * 64;
    int wc = (wid >> 1) * 64;

    float c[4][8][4];
    #pragma unroll
    for (int mi = 0; mi < 4; mi++)
        #pragma unroll
        for (int nj = 0; nj < 8; nj++)
            #pragma unroll
            for (int q = 0; q < 4; q++) c[mi][nj][q] = 0.f;

    const __half* Ab = A  + (size_t)bm * K;
    const __half* Bb = Bt + (size_t)bn * K;
    int r8 = t >> 3, c8 = t & 7;

    auto prefetch = [&](int kt, int s) {
        float* dA = smem + s * STG_WORDS;
        float* dB = dA + 128 * 48;
        size_t kofs = (size_t)kt * BKE + c8 * 8;
        unsigned da = (unsigned)__cvta_generic_to_shared(dA + r8 * 48 + c8 * 4);
        unsigned db = (unsigned)__cvta_generic_to_shared(dB + r8 * 48 + c8 * 4);
        #pragma unroll
        for (int i = 0; i < 8; i++) {
            cpa16(da + i * 16 * 48 * 4, Ab + (size_t)(r8 + i * 16) * K + kofs);
            cpa16(db + i * 16 * 48 * 4, Bb + (size_t)(r8 + i * 16) * K + kofs);
        }
    };

    int Tn = K / BKE;
    prefetch(0, 0);
    CP_COMMIT();

    for (int kt = 0; kt < Tn; kt++) {
        int s = kt & 1;
        CP_WAIT0();
        __syncthreads();
        if (kt + 1 < Tn) { prefetch(kt + 1, s ^ 1); CP_COMMIT(); }

        const float* cA = smem + s * STG_WORDS;
        const float* cB = cA + 128 * 48;
        #pragma unroll
        for (int u = 0; u < 2; u++) {
            uint4 aF[8], bF[8];
            #pragma unroll
            for (int i = 0; i < 8; i++) {
                int r = wr + (i >> 1) * 16 + g + (i & 1) * 8;
                aF[i] = *reinterpret_cast<const uint4*>(cA + r * 48 + u * 16 + tg * 4);
            }
            #pragma unroll
            for (int nj = 0; nj < 8; nj++) {
                int cc = wc + nj * 8 + g;
                bF[nj] = *reinterpret_cast<const uint4*>(cB + cc * 48 + u * 16 + tg * 4);
            }
            #pragma unroll
            for (int mi = 0; mi < 4; mi++) {
                unsigned ae[4] = {aF[2*mi].x, aF[2*mi+1].x, aF[2*mi].y, aF[2*mi+1].y};
                unsigned ao[4] = {aF[2*mi].z, aF[2*mi+1].z, aF[2*mi].w, aF[2*mi+1].w};
                #pragma unroll
                for (int nj = 0; nj < 8; nj++) {
                    mma_f16(c[mi][nj], ae, bF[nj].x, bF[nj].y);
                    mma_f16(c[mi][nj], ao, bF[nj].z, bF[nj].w);
                }
            }
        }
    }

    #pragma unroll
    for (int mi = 0; mi < 4; mi++) {
        #pragma unroll
        for (int nj = 0; nj < 8; nj++) {
            int row = bm + wr + mi * 16 + g;
            int col = bn + wc + nj * 8 + tg * 2;
            float b0 = bias[col], b1 = bias[col + 1];
            float v0 = c[mi][nj][0] + b0, v1 = c[mi][nj][1] + b1;
            float v2 = c[mi][nj][2] + b0, v3 = c[mi][nj][3] + b1;
            if (EPI == EPI_GELU) {
                v0 = 0.5f * v0 * (1.f + erff(v0 * 0.70710678118f));
                v1 = 0.5f * v1 * (1.f + erff(v1 * 0.70710678118f));
                v2 = 0.5f * v2 * (1.f + erff(v2 * 0.70710678118f));
                v3 = 0.5f * v3 * (1.f + erff(v3 * 0.70710678118f));
            }
            if (EPI == EPI_RES) {
                float2 r0 = *reinterpret_cast<const float2*>(res + (size_t)row * N + col);
                float2 r1 = *reinterpret_cast<const float2*>(res + (size_t)(row + 8) * N + col);
                v0 += r0.x; v1 += r0.y; v2 += r1.x; v3 += r1.y;
            }
            if (sizeof(TO) == 4) {
                float* Cf = (float*)C;
                *reinterpret_cast<float2*>(Cf + (size_t)row * N + col)       = make_float2(v0, v1);
                *reinterpret_cast<float2*>(Cf + (size_t)(row + 8) * N + col) = make_float2(v2, v3);
            } else {
                __half* Ch = (__half*)C;
                *reinterpret_cast<unsigned*>(Ch + (size_t)row * N + col)       = pack_f16(v0, v1);
                *reinterpret_cast<unsigned*>(Ch + (size_t)(row + 8) * N + col) = pack_f16(v2, v3);
            }
        }
    }
}

// ---------------- fp16 flash attention: cp.async + ldmatrix ------------------
// grid (L/64, N*H); 128 thr (4 warps, 16 q-rows each). KV tile 128, 2 stages.
// smem halfs: Q[64][72] @0; stage s: K[128][72] @4608+s*18432, V at +9216.
#define ATTN_SMEM ((4608 + 4*9216)*2)   // 82944 B

__global__ __launch_bounds__(128) void attn_k(const unsigned* __restrict__ mask,
                                              const __half* __restrict__ qkv) {
    extern __shared__ __half smh[];
    uint32_t base = smem_u32(smh);
    int t = threadIdx.x, w = t >> 5, lane = t & 31;
    int g = lane >> 2, tg = lane & 3;
    int qt = blockIdx.x, nh = blockIdx.y;
    int n = nh >> 4, h = nh & 15;
    size_t qrow0 = (size_t)n * LL + (size_t)qt * 64;
    int r8 = t >> 3, c8 = t & 7;

    // Q: 64x64 fp16 via cp.async (512 chunks)
    #pragma unroll
    for (int i = 0; i < 4; i++) {
        int r = r8 + i * 16;
        cpa16(base + (r * 72 + c8 * 8) * 2,
              qkv + (qrow0 + r) * 3072 + h * 64 + c8 * 8);
    }
    auto prefetchKV = [&](int kt, int s) {
        uint32_t ko = 4608 + s * 18432, vo = ko + 9216;
        size_t rowb = ((size_t)n * LL + kt * 128 + r8) * 3072 + h * 64 + c8 * 8;
        #pragma unroll
        for (int i = 0; i < 8; i++) {
            cpa16(base + (ko + (r8 + i * 16) * 72 + c8 * 8) * 2,
                  qkv + rowb + (size_t)i * 16 * 3072 + 1024);
            cpa16(base + (vo + (r8 + i * 16) * 72 + c8 * 8) * 2,
                  qkv + rowb + (size_t)i * 16 * 3072 + 2048);
        }
    };
    prefetchKV(0, 0);
    CP_COMMIT();

    float O[8][4];
    #pragma unroll
    for (int nj = 0; nj < 8; nj++)
        #pragma unroll
        for (int q = 0; q < 4; q++) O[nj][q] = 0.f;
    float l0 = 0.f, l1 = 0.f;
    unsigned aQ[4][4];
    bool qLoaded = false;

    size_t mrow = (size_t)nh * LL + (size_t)qt * 64 + w * 16;
    // ldmatrix lane geometry
    int klrow = lane & 7, ktile = lane >> 3;             // QK: tile = d-octet
    int vkv = ((lane >> 3) & 1) * 8 + (lane & 7);        // PV: kv offset
    int vd  = (lane >> 4) * 8;                           // PV: d offset

    for (int kt = 0; kt < 16; kt++) {
        int s = kt & 1;
        if (kt + 1 < 16) { prefetchKV(kt + 1, s ^ 1); CP_COMMIT(); CP_WAIT1(); }
        else             { CP_WAIT0(); }
        __syncthreads();
        if (!qLoaded) {
            qLoaded = true;
            #pragma unroll
            for (int tt = 0; tt < 4; tt++) {
                const __half* qp = smh + (w * 16 + g) * 72 + tt * 16 + 2 * tg;
                aQ[tt][0] = *reinterpret_cast<const unsigned*>(qp);
                aQ[tt][1] = *reinterpret_cast<const unsigned*>(qp + 8 * 72);
                aQ[tt][2] = *reinterpret_cast<const unsigned*>(qp + 8);
                aQ[tt][3] = *reinterpret_cast<const unsigned*>(qp + 8 * 72 + 8);
            }
        }
        uint32_t ko = 4608 + s * 18432, vo = ko + 9216;

        // S = Q K^T : 16 kv-octets x 64 d
        float sc[16][4];
        #pragma unroll
        for (int j = 0; j < 16; j++) {
            unsigned bq[2][4];
            uint32_t ka = base + ((j * 8 + klrow) * 72 + ktile * 8 + ko) * 2;
            ldsm_x4(bq[0], ka);
            ldsm_x4(bq[1], ka + 64);          // +32 halfs
            sc[j][0] = sc[j][1] = sc[j][2] = sc[j][3] = 0.f;
            #pragma unroll
            for (int tt = 0; tt < 4; tt++)
                mma_f16(sc[j], aQ[tt], bq[tt >> 1][(tt & 1) * 2], bq[tt >> 1][(tt & 1) * 2 + 1]);
        }

        // mask + exp + row sums
        int kv0 = kt * 128;
        const unsigned* mr0 = mask + (mrow + g)     * (size_t)LL + kv0;
        const unsigned* mr1 = mask + (mrow + g + 8) * (size_t)LL + kv0;
        #pragma unroll
        for (int j = 0; j < 16; j++) {
            int col = j * 8 + 2 * tg;
            uint2 p0 = *reinterpret_cast<const uint2*>(mr0 + col);
            uint2 p1 = *reinterpret_cast<const uint2*>(mr1 + col);
            sc[j][0] = p0.x ? 0.f : __expf(sc[j][0]);
            sc[j][1] = p0.y ? 0.f : __expf(sc[j][1]);
            sc[j][2] = p1.x ? 0.f : __expf(sc[j][2]);
            sc[j][3] = p1.y ? 0.f : __expf(sc[j][3]);
            l0 += sc[j][0] + sc[j][1];
            l1 += sc[j][2] + sc[j][3];
        }

        // O += P @ V  (V in [kv][d], B-frags via ldmatrix.trans)
        #pragma unroll
        for (int tt = 0; tt < 8; tt++) {
            unsigned pa[4];
            pa[0] = pack_f16(sc[2*tt    ][0], sc[2*tt    ][1]);
            pa[1] = pack_f16(sc[2*tt    ][2], sc[2*tt    ][3]);
            pa[2] = pack_f16(sc[2*tt + 1][0], sc[2*tt + 1][1]);
            pa[3] = pack_f16(sc[2*tt + 1][2], sc[2*tt + 1][3]);
            uint32_t va = base + ((tt * 16 + vkv) * 72 + vd + vo) * 2;
            #pragma unroll
            for (int njp = 0; njp < 4; njp++) {
                unsigned bv[4];
                ldsm_x4_t(bv, va + njp * 32);   // +16 halfs per njp
                mma_f16(O[2*njp    ], pa, bv[0], bv[1]);
                mma_f16(O[2*njp + 1], pa, bv[2], bv[3]);
            }
        }
        __syncthreads();
    }

    l0 += __shfl_xor_sync(0xFFFFFFFFu, l0, 1);
    l0 += __shfl_xor_sync(0xFFFFFFFFu, l0, 2);
    l1 += __shfl_xor_sync(0xFFFFFFFFu, l1, 1);
    l1 += __shfl_xor_sync(0xFFFFFFFFu, l1, 2);
    float r0 = 1.f / l0, r1 = 1.f / l1;
    size_t orow = qrow0 + w * 16 + g;
    #pragma unroll
    for (int nj = 0; nj < 8; nj++) {
        int col = h * 64 + nj * 8 + 2 * tg;
        *reinterpret_cast<unsigned*>(g_attnh + orow * EN + col) =
            pack_f16(O[nj][0] * r0, O[nj][1] * r0);
        *reinterpret_cast<unsigned*>(g_attnh + (orow + 8) * EN + col) =
            pack_f16(O[nj][2] * r1, O[nj][3] * r1);
    }
}

// ---------------- launch -----------------------------------------------------
extern "C" void kernel_launch(void* const* d_in, const int* in_sizes, int n_in,
                              void* d_out, int out_size) {
    const float* x     = (const float*)d_in[0];
    const unsigned* mask = (const unsigned*)d_in[1];
    const float* ln1_s = (const float*)d_in[2];
    const float* ln1_b = (const float*)d_in[3];
    const float* Wqkv  = (const float*)d_in[4];
    const float* bqkv  = (const float*)d_in[5];
    const float* Wo    = (const float*)d_in[6];
    const float* bo    = (const float*)d_in[7];
    const float* ln2_s = (const float*)d_in[8];
    const float* ln2_b = (const float*)d_in[9];
    const float* lnf_s = (const float*)d_in[10];
    const float* lnf_b = (const float*)d_in[11];
    const float* W1    = (const float*)d_in[12];
    const float* b1    = (const float*)d_in[13];
    const float* W2    = (const float*)d_in[14];
    const float* b2    = (const float*)d_in[15];
    float* out = (float*)d_out;

    __half *p_hh, *p_qkvh, *p_attnh, *p_h2, *p_ff, *p_Wqkvt, *p_Wot, *p_W1t, *p_W2t;
    float *p_x1, *p_bqkv;
    cudaGetSymbolAddress((void**)&p_hh,    g_hh);
    cudaGetSymbolAddress((void**)&p_qkvh,  g_qkvh);
    cudaGetSymbolAddress((void**)&p_attnh, g_attnh);
    cudaGetSymbolAddress((void**)&p_x1,    g_x1);
    cudaGetSymbolAddress((void**)&p_h2,    g_h2);
    cudaGetSymbolAddress((void**)&p_ff,    g_ff);
    cudaGetSymbolAddress((void**)&p_bqkv,  g_bqkv);
    cudaGetSymbolAddress((void**)&p_Wqkvt, g_Wqkvt);
    cudaGetSymbolAddress((void**)&p_Wot,   g_Wot);
    cudaGetSymbolAddress((void**)&p_W1t,   g_W1t);
    cudaGetSymbolAddress((void**)&p_W2t,   g_W2t);

    cudaFuncSetAttribute(gemm4_k<EPI_BIAS, __half>, cudaFuncAttributeMaxDynamicSharedMemorySize, GEMM_SMEM);
    cudaFuncSetAttribute(gemm4_k<EPI_RES,  float>,  cudaFuncAttributeMaxDynamicSharedMemorySize, GEMM_SMEM);
    cudaFuncSetAttribute(gemm4_k<EPI_GELU, __half>, cudaFuncAttributeMaxDynamicSharedMemorySize, GEMM_SMEM);
    cudaFuncSetAttribute(attn_k, cudaFuncAttributeMaxDynamicSharedMemorySize, ATTN_SMEM);

    dim3 tb(32, 8);
    transT_f16_k<<<dim3(3*EN/32, EN/32), tb>>>(Wqkv, p_Wqkvt, EN, 3*EN, EN, 0.125f);
    transT_f16_k<<<dim3(EN/32,   EN/32), tb>>>(Wo,   p_Wot,   EN, EN,   0, 1.f);
    transT_f16_k<<<dim3(DFFN/32, EN/32), tb>>>(W1,   p_W1t,   EN, DFFN, 0, 1.f);
    transT_f16_k<<<dim3(EN/32, DFFN/32), tb>>>(W2,   p_W2t,   DFFN, EN, 0, 1.f);
    scale_bias_k<<<3*EN/256, 256>>>(bqkv, p_bqkv);

    // 1. h = LN1(x) -> fp16
    ln1_k<<<ROWS, 256>>>(x, ln1_s, ln1_b, p_hh);
    // 2. qkv = h @ Wqkv + bqkv (fp16 out; q-part pre-scaled by 0.125)
    gemm4_k<EPI_BIAS, __half><<<dim3(3*EN/128, ROWS/128), 128, GEMM_SMEM>>>(
        ROWS, 3*EN, EN, p_hh, p_Wqkvt, p_bqkv, nullptr, p_qkvh);
    // 3. attention (fp16 throughout)
    attn_k<<<dim3(LL/64, NB*HHH), 128, ATTN_SMEM>>>(mask, p_qkvh);
    // 4. x1 = x + attn @ Wo + bo
    gemm4_k<EPI_RES, float><<<dim3(EN/128, ROWS/128), 128, GEMM_SMEM>>>(
        ROWS, EN, EN, p_attnh, p_Wot, bo, x, p_x1);
    // 5. h2 = LNf(LN2(x1)) -> fp16
    ln2f_k<<<ROWS, 256>>>(p_x1, ln2_s, ln2_b, lnf_s, lnf_b, p_h2);
    // 6. ff = gelu(h2 @ W1 + b1)
    gemm4_k<EPI_GELU, __half><<<dim3(DFFN/128, ROWS/128), 128, GEMM_SMEM>>>(
        ROWS, DFFN, EN, p_h2, p_W1t, b1, nullptr, p_ff);
    // 7. out = x1 + ff @ W2 + b2
    gemm4_k<EPI_RES, float><<<dim3(EN/128, ROWS/128), 128, GEMM_SMEM>>>(
        ROWS, EN, DFFN, p_ff, p_W2t, b2, p_x1, out);
}

// round 8
// speedup vs baseline: 1.6725x; 1.0006x over previous
#include <cuda_runtime.h>
#include <cuda_fp16.h>
#include <cstdint>

#define EN   1024
#define DFFN 4096
#define NB   2
#define LL   2048
#define HHH  16
#define ROWS (NB*LL)   // 4096

// ---------------- scratch (device globals; no allocation allowed) ----------
__device__ __half g_hh   [ROWS*EN];      // LN1 out (A of QKV)
__device__ __half g_qkvh [ROWS*3*EN];    // QKV projection (fp16; q pre-scaled)
__device__ __half g_attnh[ROWS*EN];      // attn out (A of Wo)
__device__ float  g_x1   [ROWS*EN];      // x + attn@Wo + bo (fp32 trunk)
__device__ __half g_h2   [ROWS*EN];      // LNf(LN2(x1)) (A of FF1)
__device__ __half g_ff   [ROWS*DFFN];    // gelu(h2@W1+b1) (A of FF2)
__device__ float  g_bqkv [3*EN];         // bqkv with q-part scaled by 0.125
// transposed fp16 weights (refreshed every launch)
__device__ __half g_Wqkvt[3*EN*EN];      // [3E][E] (q-rows pre-scaled 0.125)
__device__ __half g_Wot  [EN*EN];
__device__ __half g_W1t  [DFFN*EN];
__device__ __half g_W2t  [EN*DFFN];

// ---------------- helpers ---------------------------------------------------
__device__ __forceinline__ unsigned pack_f16(float lo, float hi) {
    __half2 p = __floats2half2_rn(lo, hi);
    return *reinterpret_cast<unsigned*>(&p);
}
__device__ __forceinline__ void mma_f16(float* c, const unsigned* a, unsigned b0, unsigned b1) {
    asm volatile(
        "mma.sync.aligned.m16n8k16.row.col.f32.f16.f16.f32 "
        "{%0,%1,%2,%3},{%4,%5,%6,%7},{%8,%9},{%0,%1,%2,%3};"
        : "+f"(c[0]), "+f"(c[1]), "+f"(c[2]), "+f"(c[3])
        : "r"(a[0]), "r"(a[1]), "r"(a[2]), "r"(a[3]), "r"(b0), "r"(b1));
}
__device__ __forceinline__ void cpa16(unsigned dst, const void* src) {
    asm volatile("cp.async.cg.shared.global [%0], [%1], 16;\n" :: "r"(dst), "l"(src));
}
#define CP_COMMIT() asm volatile("cp.async.commit_group;\n" ::)
#define CP_WAIT0()  asm volatile("cp.async.wait_group 0;\n" ::)
#define CP_WAIT1()  asm volatile("cp.async.wait_group 1;\n" ::)

__device__ __forceinline__ uint32_t smem_u32(const void* p) {
    uint32_t a;
    asm("{ .reg .u64 t; cvta.to.shared.u64 t, %1; cvt.u32.u64 %0, t; }" : "=r"(a) : "l"(p));
    return a;
}
__device__ __forceinline__ void ldsm_x4(unsigned* r, uint32_t addr) {
    asm volatile("ldmatrix.sync.aligned.m8n8.x4.shared.b16 {%0,%1,%2,%3}, [%4];"
        : "=r"(r[0]), "=r"(r[1]), "=r"(r[2]), "=r"(r[3]) : "r"(addr));
}
__device__ __forceinline__ void ldsm_x4_t(unsigned* r, uint32_t addr) {
    asm volatile("ldmatrix.sync.aligned.m8n8.x4.trans.shared.b16 {%0,%1,%2,%3}, [%4];"
        : "=r"(r[0]), "=r"(r[1]), "=r"(r[2]), "=r"(r[3]) : "r"(addr));
}

__device__ __forceinline__ void blockReduce2(float& a, float& b) {
    __shared__ float sm[16];
    #pragma unroll
    for (int o = 16; o; o >>= 1) {
        a += __shfl_xor_sync(0xFFFFFFFFu, a, o);
        b += __shfl_xor_sync(0xFFFFFFFFu, b, o);
    }
    int w = threadIdx.x >> 5, lane = threadIdx.x & 31;
    __syncthreads();
    if (lane == 0) { sm[w] = a; sm[8 + w] = b; }
    __syncthreads();
    a = 0.f; b = 0.f;
    #pragma unroll
    for (int i = 0; i < 8; i++) { a += sm[i]; b += sm[8 + i]; }
}

// ---------------- pre-pass kernels -------------------------------------------
// out[n][k] = f16(in[k][n] * (n < slim ? sc : 1)); 64x64 tiles, block 256
__global__ __launch_bounds__(256) void transT_f16_k(const float* __restrict__ in,
                                                    __half* __restrict__ out,
                                                    int K, int N, int slim, float sc) {
    __shared__ float tile[64][65];
    int k0 = blockIdx.y * 64, n0 = blockIdx.x * 64;
    int tx = threadIdx.x & 63, ty = threadIdx.x >> 6;   // (64, 4)
    #pragma unroll
    for (int i = 0; i < 64; i += 4)
        tile[ty + i][tx] = in[(size_t)(k0 + ty + i) * N + n0 + tx];
    __syncthreads();
    #pragma unroll
    for (int i = 0; i < 64; i += 4) {
        int n = n0 + ty + i;
        float v = tile[tx][ty + i];
        out[(size_t)n * K + k0 + tx] = __float2half(n < slim ? v * sc : v);
    }
}
__global__ __launch_bounds__(256) void scale_bias_k(const float* __restrict__ in,
                                                    float* __restrict__ out) {
    int i = blockIdx.x * 256 + threadIdx.x;
    out[i] = i < EN ? in[i] * 0.125f : in[i];
}

// ---------------- LN kernels -------------------------------------------------
__global__ __launch_bounds__(256) void ln1_k(const float* __restrict__ x,
                                             const float* __restrict__ s,
                                             const float* __restrict__ b,
                                             __half* __restrict__ out) {
    int row = blockIdx.x, t = threadIdx.x;
    float4 v = reinterpret_cast<const float4*>(x + (size_t)row * EN)[t];
    float sum = v.x + v.y + v.z + v.w;
    float sq  = v.x*v.x + v.y*v.y + v.z*v.z + v.w*v.w;
    blockReduce2(sum, sq);
    float mu = sum * (1.f / EN);
    float rs = rsqrtf(sq * (1.f / EN) - mu * mu + 1e-5f);
    float4 sv = reinterpret_cast<const float4*>(s)[t];
    float4 bv = reinterpret_cast<const float4*>(b)[t];
    uint2 pk;
    pk.x = pack_f16((v.x - mu) * rs * sv.x + bv.x, (v.y - mu) * rs * sv.y + bv.y);
    pk.y = pack_f16((v.z - mu) * rs * sv.z + bv.z, (v.w - mu) * rs * sv.w + bv.w);
    reinterpret_cast<uint2*>(out + (size_t)row * EN)[t] = pk;
}

__global__ __launch_bounds__(256) void ln2f_k(const float* __restrict__ x,
                                              const float* __restrict__ s2,
                                              const float* __restrict__ b2,
                                              const float* __restrict__ sf,
                                              const float* __restrict__ bf,
                                              __half* __restrict__ out) {
    int row = blockIdx.x, t = threadIdx.x;
    float4 v = reinterpret_cast<const float4*>(x + (size_t)row * EN)[t];
    float sum = v.x + v.y + v.z + v.w;
    float sq  = v.x*v.x + v.y*v.y + v.z*v.z + v.w*v.w;
    blockReduce2(sum, sq);
    float mu = sum * (1.f / EN);
    float rs = rsqrtf(sq * (1.f / EN) - mu * mu + 1e-5f);
    float4 sv = reinterpret_cast<const float4*>(s2)[t];
    float4 bv = reinterpret_cast<const float4*>(b2)[t];
    float4 y;
    y.x = (v.x - mu) * rs * sv.x + bv.x;
    y.y = (v.y - mu) * rs * sv.y + bv.y;
    y.z = (v.z - mu) * rs * sv.z + bv.z;
    y.w = (v.w - mu) * rs * sv.w + bv.w;
    float sum2 = y.x + y.y + y.z + y.w;
    float sq2  = y.x*y.x + y.y*y.y + y.z*y.z + y.w*y.w;
    blockReduce2(sum2, sq2);
    float mu2 = sum2 * (1.f / EN);
    float rs2 = rsqrtf(sq2 * (1.f / EN) - mu2 * mu2 + 1e-5f);
    float4 fv = reinterpret_cast<const float4*>(sf)[t];
    float4 gv = reinterpret_cast<const float4*>(bf)[t];
    uint2 pk;
    pk.x = pack_f16((y.x - mu2) * rs2 * fv.x + gv.x, (y.y - mu2) * rs2 * fv.y + gv.y);
    pk.y = pack_f16((y.z - mu2) * rs2 * fv.z + gv.z, (y.w - mu2) * rs2 * fv.w + gv.w);
    reinterpret_cast<uint2*>(out + (size_t)row * EN)[t] = pk;
}

// ---------------- fp16 GEMM (unchanged from R7) ------------------------------
#define EPI_BIAS 0
#define EPI_GELU 1
#define EPI_RES  2

#define STG_WORDS (2*128*48)
#define GEMM_SMEM (2*STG_WORDS*4)

template <int EPI, typename TO>
__global__ __launch_bounds__(128, 2) void gemm4_k(int M, int N, int K,
                                                  const __half* __restrict__ A,
                                                  const __half* __restrict__ Bt,
                                                  const float* __restrict__ bias,
                                                  const float* __restrict__ res,
                                                  TO* __restrict__ C) {
    extern __shared__ float smem[];
    constexpr int BKE = 64;
    int bm = blockIdx.y * 128, bn = blockIdx.x * 128;
    int t = threadIdx.x, wid = t >> 5, lane = t & 31;
    int g = lane >> 2, tg = lane & 3;
    int wr = (wid & 1) * 64;
    int wc = (wid >> 1) * 64;

    float c[4][8][4];
    #pragma unroll
    for (int mi = 0; mi < 4; mi++)
        #pragma unroll
        for (int nj = 0; nj < 8; nj++)
            #pragma unroll
            for (int q = 0; q < 4; q++) c[mi][nj][q] = 0.f;

    const __half* Ab = A  + (size_t)bm * K;
    const __half* Bb = Bt + (size_t)bn * K;
    int r8 = t >> 3, c8 = t & 7;

    auto prefetch = [&](int kt, int s) {
        float* dA = smem + s * STG_WORDS;
        float* dB = dA + 128 * 48;
        size_t kofs = (size_t)kt * BKE + c8 * 8;
        unsigned da = (unsigned)__cvta_generic_to_shared(dA + r8 * 48 + c8 * 4);
        unsigned db = (unsigned)__cvta_generic_to_shared(dB + r8 * 48 + c8 * 4);
        #pragma unroll
        for (int i = 0; i < 8; i++) {
            cpa16(da + i * 16 * 48 * 4, Ab + (size_t)(r8 + i * 16) * K + kofs);
            cpa16(db + i * 16 * 48 * 4, Bb + (size_t)(r8 + i * 16) * K + kofs);
        }
    };

    int Tn = K / BKE;
    prefetch(0, 0);
    CP_COMMIT();

    for (int kt = 0; kt < Tn; kt++) {
        int s = kt & 1;
        CP_WAIT0();
        __syncthreads();
        if (kt + 1 < Tn) { prefetch(kt + 1, s ^ 1); CP_COMMIT(); }

        const float* cA = smem + s * STG_WORDS;
        const float* cB = cA + 128 * 48;
        #pragma unroll
        for (int u = 0; u < 2; u++) {
            uint4 aF[8], bF[8];
            #pragma unroll
            for (int i = 0; i < 8; i++) {
                int r = wr + (i >> 1) * 16 + g + (i & 1) * 8;
                aF[i] = *reinterpret_cast<const uint4*>(cA + r * 48 + u * 16 + tg * 4);
            }
            #pragma unroll
            for (int nj = 0; nj < 8; nj++) {
                int cc = wc + nj * 8 + g;
                bF[nj] = *reinterpret_cast<const uint4*>(cB + cc * 48 + u * 16 + tg * 4);
            }
            #pragma unroll
            for (int mi = 0; mi < 4; mi++) {
                unsigned ae[4] = {aF[2*mi].x, aF[2*mi+1].x, aF[2*mi].y, aF[2*mi+1].y};
                unsigned ao[4] = {aF[2*mi].z, aF[2*mi+1].z, aF[2*mi].w, aF[2*mi+1].w};
                #pragma unroll
                for (int nj = 0; nj < 8; nj++) {
                    mma_f16(c[mi][nj], ae, bF[nj].x, bF[nj].y);
                    mma_f16(c[mi][nj], ao, bF[nj].z, bF[nj].w);
                }
            }
        }
    }

    #pragma unroll
    for (int mi = 0; mi < 4; mi++) {
        #pragma unroll
        for (int nj = 0; nj < 8; nj++) {
            int row = bm + wr + mi * 16 + g;
            int col = bn + wc + nj * 8 + tg * 2;
            float b0 = bias[col], b1 = bias[col + 1];
            float v0 = c[mi][nj][0] + b0, v1 = c[mi][nj][1] + b1;
            float v2 = c[mi][nj][2] + b0, v3 = c[mi][nj][3] + b1;
            if (EPI == EPI_GELU) {
                v0 = 0.5f * v0 * (1.f + erff(v0 * 0.70710678118f));
                v1 = 0.5f * v1 * (1.f + erff(v1 * 0.70710678118f));
                v2 = 0.5f * v2 * (1.f + erff(v2 * 0.70710678118f));
                v3 = 0.5f * v3 * (1.f + erff(v3 * 0.70710678118f));
            }
            if (EPI == EPI_RES) {
                float2 r0 = *reinterpret_cast<const float2*>(res + (size_t)row * N + col);
                float2 r1 = *reinterpret_cast<const float2*>(res + (size_t)(row + 8) * N + col);
                v0 += r0.x; v1 += r0.y; v2 += r1.x; v3 += r1.y;
            }
            if (sizeof(TO) == 4) {
                float* Cf = (float*)C;
                *reinterpret_cast<float2*>(Cf + (size_t)row * N + col)       = make_float2(v0, v1);
                *reinterpret_cast<float2*>(Cf + (size_t)(row + 8) * N + col) = make_float2(v2, v3);
            } else {
                __half* Ch = (__half*)C;
                *reinterpret_cast<unsigned*>(Ch + (size_t)row * N + col)       = pack_f16(v0, v1);
                *reinterpret_cast<unsigned*>(Ch + (size_t)(row + 8) * N + col) = pack_f16(v2, v3);
            }
        }
    }
}

// ---------------- fp16 flash attention: q-tile 128, 256 threads --------------
// grid (L/128, N*H); 8 warps x 16 q-rows. KV tile 128, 2 stages.
// smem halfs: Q[128][72] @0; stage s: K[128][72] @9216+s*18432, V at +9216.
#define ATTN_SMEM ((9216 + 2*18432)*2)   // 92160 B

__global__ __launch_bounds__(256) void attn_k(const unsigned* __restrict__ mask,
                                              const __half* __restrict__ qkv) {
    extern __shared__ __half smh[];
    uint32_t base = smem_u32(smh);
    int t = threadIdx.x, w = t >> 5, lane = t & 31;
    int g = lane >> 2, tg = lane & 3;
    int qt = blockIdx.x, nh = blockIdx.y;
    int n = nh >> 4, h = nh & 15;
    size_t qrow0 = (size_t)n * LL + (size_t)qt * 128;
    int r8 = t >> 3, c8 = t & 7;      // r8: 0..31

    // Q: 128x64 fp16 via cp.async (1024 chunks, 4/thread)
    #pragma unroll
    for (int i = 0; i < 4; i++) {
        int r = r8 + i * 32;
        cpa16(base + (r * 72 + c8 * 8) * 2,
              qkv + (qrow0 + r) * 3072 + h * 64 + c8 * 8);
    }
    auto prefetchKV = [&](int kt, int s) {
        uint32_t ko = 9216 + s * 18432, vo = ko + 9216;
        size_t rowb = ((size_t)n * LL + kt * 128 + r8) * 3072 + h * 64 + c8 * 8;
        #pragma unroll
        for (int i = 0; i < 4; i++) {
            cpa16(base + (ko + (r8 + i * 32) * 72 + c8 * 8) * 2,
                  qkv + rowb + (size_t)i * 32 * 3072 + 1024);
            cpa16(base + (vo + (r8 + i * 32) * 72 + c8 * 8) * 2,
                  qkv + rowb + (size_t)i * 32 * 3072 + 2048);
        }
    };
    prefetchKV(0, 0);
    CP_COMMIT();

    float O[8][4];
    #pragma unroll
    for (int nj = 0; nj < 8; nj++)
        #pragma unroll
        for (int q = 0; q < 4; q++) O[nj][q] = 0.f;
    float l0 = 0.f, l1 = 0.f;
    unsigned aQ[4][4];
    bool qLoaded = false;

    size_t mrow = (size_t)nh * LL + (size_t)qt * 128 + w * 16;
    int klrow = lane & 7, ktile = lane >> 3;
    int vkv = ((lane >> 3) & 1) * 8 + (lane & 7);
    int vd  = (lane >> 4) * 8;

    for (int kt = 0; kt < 16; kt++) {
        int s = kt & 1;
        if (kt + 1 < 16) { prefetchKV(kt + 1, s ^ 1); CP_COMMIT(); CP_WAIT1(); }
        else             { CP_WAIT0(); }
        __syncthreads();
        if (!qLoaded) {
            qLoaded = true;
            #pragma unroll
            for (int tt = 0; tt < 4; tt++) {
                const __half* qp = smh + (w * 16 + g) * 72 + tt * 16 + 2 * tg;
                aQ[tt][0] = *reinterpret_cast<const unsigned*>(qp);
                aQ[tt][1] = *reinterpret_cast<const unsigned*>(qp + 8 * 72);
                aQ[tt][2] = *reinterpret_cast<const unsigned*>(qp + 8);
                aQ[tt][3] = *reinterpret_cast<const unsigned*>(qp + 8 * 72 + 8);
            }
        }
        uint32_t ko = 9216 + s * 18432, vo = ko + 9216;

        // S = Q K^T
        float sc[16][4];
        #pragma unroll
        for (int j = 0; j < 16; j++) {
            unsigned bq[2][4];
            uint32_t ka = base + ((j * 8 + klrow) * 72 + ktile * 8 + ko) * 2;
            ldsm_x4(bq[0], ka);
            ldsm_x4(bq[1], ka + 64);
            sc[j][0] = sc[j][1] = sc[j][2] = sc[j][3] = 0.f;
            #pragma unroll
            for (int tt = 0; tt < 4; tt++)
                mma_f16(sc[j], aQ[tt], bq[tt >> 1][(tt & 1) * 2], bq[tt >> 1][(tt & 1) * 2 + 1]);
        }

        // mask + exp + row sums
        int kv0 = kt * 128;
        const unsigned* mr0 = mask + (mrow + g)     * (size_t)LL + kv0;
        const unsigned* mr1 = mask + (mrow + g + 8) * (size_t)LL + kv0;
        #pragma unroll
        for (int j = 0; j < 16; j++) {
            int col = j * 8 + 2 * tg;
            uint2 p0 = *reinterpret_cast<const uint2*>(mr0 + col);
            uint2 p1 = *reinterpret_cast<const uint2*>(mr1 + col);
            sc[j][0] = p0.x ? 0.f : __expf(sc[j][0]);
            sc[j][1] = p0.y ? 0.f : __expf(sc[j][1]);
            sc[j][2] = p1.x ? 0.f : __expf(sc[j][2]);
            sc[j][3] = p1.y ? 0.f : __expf(sc[j][3]);
            l0 += sc[j][0] + sc[j][1];
            l1 += sc[j][2] + sc[j][3];
        }

        // O += P @ V
        #pragma unroll
        for (int tt = 0; tt < 8; tt++) {
            unsigned pa[4];
            pa[0] = pack_f16(sc[2*tt    ][0], sc[2*tt    ][1]);
            pa[1] = pack_f16(sc[2*tt    ][2], sc[2*tt    ][3]);
            pa[2] = pack_f16(sc[2*tt + 1][0], sc[2*tt + 1][1]);
            pa[3] = pack_f16(sc[2*tt + 1][2], sc[2*tt + 1][3]);
            uint32_t va = base + ((tt * 16 + vkv) * 72 + vd + vo) * 2;
            #pragma unroll
            for (int njp = 0; njp < 4; njp++) {
                unsigned bv[4];
                ldsm_x4_t(bv, va + njp * 32);
                mma_f16(O[2*njp    ], pa, bv[0], bv[1]);
                mma_f16(O[2*njp + 1], pa, bv[2], bv[3]);
            }
        }
        __syncthreads();
    }

    l0 += __shfl_xor_sync(0xFFFFFFFFu, l0, 1);
    l0 += __shfl_xor_sync(0xFFFFFFFFu, l0, 2);
    l1 += __shfl_xor_sync(0xFFFFFFFFu, l1, 1);
    l1 += __shfl_xor_sync(0xFFFFFFFFu, l1, 2);
    float r0 = 1.f / l0, r1 = 1.f / l1;
    size_t orow = qrow0 + w * 16 + g;
    #pragma unroll
    for (int nj = 0; nj < 8; nj++) {
        int col = h * 64 + nj * 8 + 2 * tg;
        *reinterpret_cast<unsigned*>(g_attnh + orow * EN + col) =
            pack_f16(O[nj][0] * r0, O[nj][1] * r0);
        *reinterpret_cast<unsigned*>(g_attnh + (orow + 8) * EN + col) =
            pack_f16(O[nj][2] * r1, O[nj][3] * r1);
    }
}

// ---------------- launch -----------------------------------------------------
extern "C" void kernel_launch(void* const* d_in, const int* in_sizes, int n_in,
                              void* d_out, int out_size) {
    const float* x     = (const float*)d_in[0];
    const unsigned* mask = (const unsigned*)d_in[1];
    const float* ln1_s = (const float*)d_in[2];
    const float* ln1_b = (const float*)d_in[3];
    const float* Wqkv  = (const float*)d_in[4];
    const float* bqkv  = (const float*)d_in[5];
    const float* Wo    = (const float*)d_in[6];
    const float* bo    = (const float*)d_in[7];
    const float* ln2_s = (const float*)d_in[8];
    const float* ln2_b = (const float*)d_in[9];
    const float* lnf_s = (const float*)d_in[10];
    const float* lnf_b = (const float*)d_in[11];
    const float* W1    = (const float*)d_in[12];
    const float* b1    = (const float*)d_in[13];
    const float* W2    = (const float*)d_in[14];
    const float* b2    = (const float*)d_in[15];
    float* out = (float*)d_out;

    __half *p_hh, *p_qkvh, *p_attnh, *p_h2, *p_ff, *p_Wqkvt, *p_Wot, *p_W1t, *p_W2t;
    float *p_x1, *p_bqkv;
    cudaGetSymbolAddress((void**)&p_hh,    g_hh);
    cudaGetSymbolAddress((void**)&p_qkvh,  g_qkvh);
    cudaGetSymbolAddress((void**)&p_attnh, g_attnh);
    cudaGetSymbolAddress((void**)&p_x1,    g_x1);
    cudaGetSymbolAddress((void**)&p_h2,    g_h2);
    cudaGetSymbolAddress((void**)&p_ff,    g_ff);
    cudaGetSymbolAddress((void**)&p_bqkv,  g_bqkv);
    cudaGetSymbolAddress((void**)&p_Wqkvt, g_Wqkvt);
    cudaGetSymbolAddress((void**)&p_Wot,   g_Wot);
    cudaGetSymbolAddress((void**)&p_W1t,   g_W1t);
    cudaGetSymbolAddress((void**)&p_W2t,   g_W2t);

    cudaFuncSetAttribute(gemm4_k<EPI_BIAS, __half>, cudaFuncAttributeMaxDynamicSharedMemorySize, GEMM_SMEM);
    cudaFuncSetAttribute(gemm4_k<EPI_RES,  float>,  cudaFuncAttributeMaxDynamicSharedMemorySize, GEMM_SMEM);
    cudaFuncSetAttribute(gemm4_k<EPI_GELU, __half>, cudaFuncAttributeMaxDynamicSharedMemorySize, GEMM_SMEM);
    cudaFuncSetAttribute(attn_k, cudaFuncAttributeMaxDynamicSharedMemorySize, ATTN_SMEM);

    dim3 tb(256);
    transT_f16_k<<<dim3(3*EN/64, EN/64), tb>>>(Wqkv, p_Wqkvt, EN, 3*EN, EN, 0.125f);
    transT_f16_k<<<dim3(EN/64,   EN/64), tb>>>(Wo,   p_Wot,   EN, EN,   0, 1.f);
    transT_f16_k<<<dim3(DFFN/64, EN/64), tb>>>(W1,   p_W1t,   EN, DFFN, 0, 1.f);
    transT_f16_k<<<dim3(EN/64, DFFN/64), tb>>>(W2,   p_W2t,   DFFN, EN, 0, 1.f);
    scale_bias_k<<<3*EN/256, 256>>>(bqkv, p_bqkv);

    // 1. h = LN1(x) -> fp16
    ln1_k<<<ROWS, 256>>>(x, ln1_s, ln1_b, p_hh);
    // 2. qkv = h @ Wqkv + bqkv (fp16 out; q pre-scaled)
    gemm4_k<EPI_BIAS, __half><<<dim3(3*EN/128, ROWS/128), 128, GEMM_SMEM>>>(
        ROWS, 3*EN, EN, p_hh, p_Wqkvt, p_bqkv, nullptr, p_qkvh);
    // 3. attention
    attn_k<<<dim3(LL/128, NB*HHH), 256, ATTN_SMEM>>>(mask, p_qkvh);
    // 4. x1 = x + attn @ Wo + bo
    gemm4_k<EPI_RES, float><<<dim3(EN/128, ROWS/128), 128, GEMM_SMEM>>>(
        ROWS, EN, EN, p_attnh, p_Wot, bo, x, p_x1);
    // 5. h2 = LNf(LN2(x1)) -> fp16
    ln2f_k<<<ROWS, 256>>>(p_x1, ln2_s, ln2_b, lnf_s, lnf_b, p_h2);
    // 6. ff = gelu(h2 @ W1 + b1)
    gemm4_k<EPI_GELU, __half><<<dim3(DFFN/128, ROWS/128), 128, GEMM_SMEM>>>(
        ROWS, DFFN, EN, p_h2, p_W1t, b1, nullptr, p_ff);
    // 7. out = x1 + ff @ W2 + b2
    gemm4_k<EPI_RES, float><<<dim3(EN/128, ROWS/128), 128, GEMM_SMEM>>>(
        ROWS, EN, DFFN, p_ff, p_W2t, b2, p_x1, out);
}

// round 9
// speedup vs baseline: 1.8793x; 1.1236x over previous
#include <cuda_runtime.h>
#include <cuda_fp16.h>
#include <cstdint>

#define EN   1024
#define DFFN 4096
#define NB   2
#define LL   2048
#define HHH  16
#define ROWS (NB*LL)   // 4096
#define PMW  (NB*HHH*LL*LL/32)   // packed mask words: 4194304

// ---------------- scratch (device globals; no allocation allowed) ----------
__device__ __half g_hh   [ROWS*EN];      // LN1 out (A of QKV)
__device__ __half g_qkvh [ROWS*3*EN];    // QKV projection (fp16; q pre-scaled)
__device__ __half g_attnh[ROWS*EN];      // attn out (A of Wo)
__device__ float  g_x1   [ROWS*EN];      // x + attn@Wo + bo (fp32 trunk)
__device__ __half g_h2   [ROWS*EN];      // LNf(LN2(x1)) (A of FF1)
__device__ __half g_ff   [ROWS*DFFN];    // gelu(h2@W1+b1) (A of FF2)
__device__ float  g_bqkv [3*EN];         // bqkv with q-part scaled by 0.125
__device__ unsigned g_pmask[PMW];        // bit-packed attn mask
// transposed fp16 weights (refreshed every launch)
__device__ __half g_Wqkvt[3*EN*EN];      // [3E][E] (q-rows pre-scaled 0.125)
__device__ __half g_Wot  [EN*EN];
__device__ __half g_W1t  [DFFN*EN];
__device__ __half g_W2t  [EN*DFFN];

// ---------------- helpers ---------------------------------------------------
__device__ __forceinline__ unsigned pack_f16(float lo, float hi) {
    __half2 p = __floats2half2_rn(lo, hi);
    return *reinterpret_cast<unsigned*>(&p);
}
__device__ __forceinline__ void mma_f16(float* c, const unsigned* a, unsigned b0, unsigned b1) {
    asm volatile(
        "mma.sync.aligned.m16n8k16.row.col.f32.f16.f16.f32 "
        "{%0,%1,%2,%3},{%4,%5,%6,%7},{%8,%9},{%0,%1,%2,%3};"
        : "+f"(c[0]), "+f"(c[1]), "+f"(c[2]), "+f"(c[3])
        : "r"(a[0]), "r"(a[1]), "r"(a[2]), "r"(a[3]), "r"(b0), "r"(b1));
}
__device__ __forceinline__ void cpa16(unsigned dst, const void* src) {
    asm volatile("cp.async.cg.shared.global [%0], [%1], 16;\n" :: "r"(dst), "l"(src));
}
#define CP_COMMIT() asm volatile("cp.async.commit_group;\n" ::)
#define CP_WAIT0()  asm volatile("cp.async.wait_group 0;\n" ::)
#define CP_WAIT1()  asm volatile("cp.async.wait_group 1;\n" ::)

__device__ __forceinline__ uint32_t smem_u32(const void* p) {
    uint32_t a;
    asm("{ .reg .u64 t; cvta.to.shared.u64 t, %1; cvt.u32.u64 %0, t; }" : "=r"(a) : "l"(p));
    return a;
}
__device__ __forceinline__ void ldsm_x4(unsigned* r, uint32_t addr) {
    asm volatile("ldmatrix.sync.aligned.m8n8.x4.shared.b16 {%0,%1,%2,%3}, [%4];"
        : "=r"(r[0]), "=r"(r[1]), "=r"(r[2]), "=r"(r[3]) : "r"(addr));
}
__device__ __forceinline__ void ldsm_x4_t(unsigned* r, uint32_t addr) {
    asm volatile("ldmatrix.sync.aligned.m8n8.x4.trans.shared.b16 {%0,%1,%2,%3}, [%4];"
        : "=r"(r[0]), "=r"(r[1]), "=r"(r[2]), "=r"(r[3]) : "r"(addr));
}

__device__ __forceinline__ void blockReduce2(float& a, float& b) {
    __shared__ float sm[16];
    #pragma unroll
    for (int o = 16; o; o >>= 1) {
        a += __shfl_xor_sync(0xFFFFFFFFu, a, o);
        b += __shfl_xor_sync(0xFFFFFFFFu, b, o);
    }
    int w = threadIdx.x >> 5, lane = threadIdx.x & 31;
    __syncthreads();
    if (lane == 0) { sm[w] = a; sm[8 + w] = b; }
    __syncthreads();
    a = 0.f; b = 0.f;
    #pragma unroll
    for (int i = 0; i < 8; i++) { a += sm[i]; b += sm[8 + i]; }
}

// ---------------- mask bit-pack: 32 int32 words -> 1 uint32 ------------------
__global__ __launch_bounds__(256) void maskpack_k(const uint4* __restrict__ in,
                                                  unsigned* __restrict__ out) {
    int o = blockIdx.x * 256 + threadIdx.x;
    const uint4* p = in + (size_t)o * 8;
    unsigned m = 0;
    #pragma unroll
    for (int i = 0; i < 8; i++) {
        uint4 v = p[i];
        m |= (v.x ? 1u : 0u) << (i * 4 + 0);
        m |= (v.y ? 1u : 0u) << (i * 4 + 1);
        m |= (v.z ? 1u : 0u) << (i * 4 + 2);
        m |= (v.w ? 1u : 0u) << (i * 4 + 3);
    }
    out[o] = m;
}

// ---------------- pre-pass kernels -------------------------------------------
__global__ __launch_bounds__(256) void transT_f16_k(const float* __restrict__ in,
                                                    __half* __restrict__ out,
                                                    int K, int N, int slim, float sc) {
    __shared__ float tile[64][65];
    int k0 = blockIdx.y * 64, n0 = blockIdx.x * 64;
    int tx = threadIdx.x & 63, ty = threadIdx.x >> 6;
    #pragma unroll
    for (int i = 0; i < 64; i += 4)
        tile[ty + i][tx] = in[(size_t)(k0 + ty + i) * N + n0 + tx];
    __syncthreads();
    #pragma unroll
    for (int i = 0; i < 64; i += 4) {
        int n = n0 + ty + i;
        float v = tile[tx][ty + i];
        out[(size_t)n * K + k0 + tx] = __float2half(n < slim ? v * sc : v);
    }
}
__global__ __launch_bounds__(256) void scale_bias_k(const float* __restrict__ in,
                                                    float* __restrict__ out) {
    int i = blockIdx.x * 256 + threadIdx.x;
    out[i] = i < EN ? in[i] * 0.125f : in[i];
}

// ---------------- LN kernels -------------------------------------------------
__global__ __launch_bounds__(256) void ln1_k(const float* __restrict__ x,
                                             const float* __restrict__ s,
                                             const float* __restrict__ b,
                                             __half* __restrict__ out) {
    int row = blockIdx.x, t = threadIdx.x;
    float4 v = reinterpret_cast<const float4*>(x + (size_t)row * EN)[t];
    float sum = v.x + v.y + v.z + v.w;
    float sq  = v.x*v.x + v.y*v.y + v.z*v.z + v.w*v.w;
    blockReduce2(sum, sq);
    float mu = sum * (1.f / EN);
    float rs = rsqrtf(sq * (1.f / EN) - mu * mu + 1e-5f);
    float4 sv = reinterpret_cast<const float4*>(s)[t];
    float4 bv = reinterpret_cast<const float4*>(b)[t];
    uint2 pk;
    pk.x = pack_f16((v.x - mu) * rs * sv.x + bv.x, (v.y - mu) * rs * sv.y + bv.y);
    pk.y = pack_f16((v.z - mu) * rs * sv.z + bv.z, (v.w - mu) * rs * sv.w + bv.w);
    reinterpret_cast<uint2*>(out + (size_t)row * EN)[t] = pk;
}

__global__ __launch_bounds__(256) void ln2f_k(const float* __restrict__ x,
                                              const float* __restrict__ s2,
                                              const float* __restrict__ b2,
                                              const float* __restrict__ sf,
                                              const float* __restrict__ bf,
                                              __half* __restrict__ out) {
    int row = blockIdx.x, t = threadIdx.x;
    float4 v = reinterpret_cast<const float4*>(x + (size_t)row * EN)[t];
    float sum = v.x + v.y + v.z + v.w;
    float sq  = v.x*v.x + v.y*v.y + v.z*v.z + v.w*v.w;
    blockReduce2(sum, sq);
    float mu = sum * (1.f / EN);
    float rs = rsqrtf(sq * (1.f / EN) - mu * mu + 1e-5f);
    float4 sv = reinterpret_cast<const float4*>(s2)[t];
    float4 bv = reinterpret_cast<const float4*>(b2)[t];
    float4 y;
    y.x = (v.x - mu) * rs * sv.x + bv.x;
    y.y = (v.y - mu) * rs * sv.y + bv.y;
    y.z = (v.z - mu) * rs * sv.z + bv.z;
    y.w = (v.w - mu) * rs * sv.w + bv.w;
    float sum2 = y.x + y.y + y.z + y.w;
    float sq2  = y.x*y.x + y.y*y.y + y.z*y.z + y.w*y.w;
    blockReduce2(sum2, sq2);
    float mu2 = sum2 * (1.f / EN);
    float rs2 = rsqrtf(sq2 * (1.f / EN) - mu2 * mu2 + 1e-5f);
    float4 fv = reinterpret_cast<const float4*>(sf)[t];
    float4 gv = reinterpret_cast<const float4*>(bf)[t];
    uint2 pk;
    pk.x = pack_f16((y.x - mu2) * rs2 * fv.x + gv.x, (y.y - mu2) * rs2 * fv.y + gv.y);
    pk.y = pack_f16((y.z - mu2) * rs2 * fv.z + gv.z, (y.w - mu2) * rs2 * fv.w + gv.w);
    reinterpret_cast<uint2*>(out + (size_t)row * EN)[t] = pk;
}

// ---------------- fp16 GEMM (unchanged from R7) ------------------------------
#define EPI_BIAS 0
#define EPI_GELU 1
#define EPI_RES  2

#define STG_WORDS (2*128*48)
#define GEMM_SMEM (2*STG_WORDS*4)

template <int EPI, typename TO>
__global__ __launch_bounds__(128, 2) void gemm4_k(int M, int N, int K,
                                                  const __half* __restrict__ A,
                                                  const __half* __restrict__ Bt,
                                                  const float* __restrict__ bias,
                                                  const float* __restrict__ res,
                                                  TO* __restrict__ C) {
    extern __shared__ float smem[];
    constexpr int BKE = 64;
    int bm = blockIdx.y * 128, bn = blockIdx.x * 128;
    int t = threadIdx.x, wid = t >> 5, lane = t & 31;
    int g = lane >> 2, tg = lane & 3;
    int wr = (wid & 1) * 64;
    int wc = (wid >> 1) * 64;

    float c[4][8][4];
    #pragma unroll
    for (int mi = 0; mi < 4; mi++)
        #pragma unroll
        for (int nj = 0; nj < 8; nj++)
            #pragma unroll
            for (int q = 0; q < 4; q++) c[mi][nj][q] = 0.f;

    const __half* Ab = A  + (size_t)bm * K;
    const __half* Bb = Bt + (size_t)bn * K;
    int r8 = t >> 3, c8 = t & 7;

    auto prefetch = [&](int kt, int s) {
        float* dA = smem + s * STG_WORDS;
        float* dB = dA + 128 * 48;
        size_t kofs = (size_t)kt * BKE + c8 * 8;
        unsigned da = (unsigned)__cvta_generic_to_shared(dA + r8 * 48 + c8 * 4);
        unsigned db = (unsigned)__cvta_generic_to_shared(dB + r8 * 48 + c8 * 4);
        #pragma unroll
        for (int i = 0; i < 8; i++) {
            cpa16(da + i * 16 * 48 * 4, Ab + (size_t)(r8 + i * 16) * K + kofs);
            cpa16(db + i * 16 * 48 * 4, Bb + (size_t)(r8 + i * 16) * K + kofs);
        }
    };

    int Tn = K / BKE;
    prefetch(0, 0);
    CP_COMMIT();

    for (int kt = 0; kt < Tn; kt++) {
        int s = kt & 1;
        CP_WAIT0();
        __syncthreads();
        if (kt + 1 < Tn) { prefetch(kt + 1, s ^ 1); CP_COMMIT(); }

        const float* cA = smem + s * STG_WORDS;
        const float* cB = cA + 128 * 48;
        #pragma unroll
        for (int u = 0; u < 2; u++) {
            uint4 aF[8], bF[8];
            #pragma unroll
            for (int i = 0; i < 8; i++) {
                int r = wr + (i >> 1) * 16 + g + (i & 1) * 8;
                aF[i] = *reinterpret_cast<const uint4*>(cA + r * 48 + u * 16 + tg * 4);
            }
            #pragma unroll
            for (int nj = 0; nj < 8; nj++) {
                int cc = wc + nj * 8 + g;
                bF[nj] = *reinterpret_cast<const uint4*>(cB + cc * 48 + u * 16 + tg * 4);
            }
            #pragma unroll
            for (int mi = 0; mi < 4; mi++) {
                unsigned ae[4] = {aF[2*mi].x, aF[2*mi+1].x, aF[2*mi].y, aF[2*mi+1].y};
                unsigned ao[4] = {aF[2*mi].z, aF[2*mi+1].z, aF[2*mi].w, aF[2*mi+1].w};
                #pragma unroll
                for (int nj = 0; nj < 8; nj++) {
                    mma_f16(c[mi][nj], ae, bF[nj].x, bF[nj].y);
                    mma_f16(c[mi][nj], ao, bF[nj].z, bF[nj].w);
                }
            }
        }
    }

    #pragma unroll
    for (int mi = 0; mi < 4; mi++) {
        #pragma unroll
        for (int nj = 0; nj < 8; nj++) {
            int row = bm + wr + mi * 16 + g;
            int col = bn + wc + nj * 8 + tg * 2;
            float b0 = bias[col], b1 = bias[col + 1];
            float v0 = c[mi][nj][0] + b0, v1 = c[mi][nj][1] + b1;
            float v2 = c[mi][nj][2] + b0, v3 = c[mi][nj][3] + b1;
            if (EPI == EPI_GELU) {
                v0 = 0.5f * v0 * (1.f + erff(v0 * 0.70710678118f));
                v1 = 0.5f * v1 * (1.f + erff(v1 * 0.70710678118f));
                v2 = 0.5f * v2 * (1.f + erff(v2 * 0.70710678118f));
                v3 = 0.5f * v3 * (1.f + erff(v3 * 0.70710678118f));
            }
            if (EPI == EPI_RES) {
                float2 r0 = *reinterpret_cast<const float2*>(res + (size_t)row * N + col);
                float2 r1 = *reinterpret_cast<const float2*>(res + (size_t)(row + 8) * N + col);
                v0 += r0.x; v1 += r0.y; v2 += r1.x; v3 += r1.y;
            }
            if (sizeof(TO) == 4) {
                float* Cf = (float*)C;
                *reinterpret_cast<float2*>(Cf + (size_t)row * N + col)       = make_float2(v0, v1);
                *reinterpret_cast<float2*>(Cf + (size_t)(row + 8) * N + col) = make_float2(v2, v3);
            } else {
                __half* Ch = (__half*)C;
                *reinterpret_cast<unsigned*>(Ch + (size_t)row * N + col)       = pack_f16(v0, v1);
                *reinterpret_cast<unsigned*>(Ch + (size_t)(row + 8) * N + col) = pack_f16(v2, v3);
            }
        }
    }
}

// ---------------- fp16 flash attention with bit-packed mask ------------------
// grid (L/128, N*H); 8 warps x 16 q-rows. KV tile 128, 2 stages.
#define ATTN_SMEM ((9216 + 2*18432)*2)   // 92160 B

__global__ __launch_bounds__(256) void attn_k(const unsigned* __restrict__ pm,
                                              const __half* __restrict__ qkv) {
    extern __shared__ __half smh[];
    uint32_t base = smem_u32(smh);
    int t = threadIdx.x, w = t >> 5, lane = t & 31;
    int g = lane >> 2, tg = lane & 3;
    int qt = blockIdx.x, nh = blockIdx.y;
    int n = nh >> 4, h = nh & 15;
    size_t qrow0 = (size_t)n * LL + (size_t)qt * 128;
    int r8 = t >> 3, c8 = t & 7;

    #pragma unroll
    for (int i = 0; i < 4; i++) {
        int r = r8 + i * 32;
        cpa16(base + (r * 72 + c8 * 8) * 2,
              qkv + (qrow0 + r) * 3072 + h * 64 + c8 * 8);
    }
    auto prefetchKV = [&](int kt, int s) {
        uint32_t ko = 9216 + s * 18432, vo = ko + 9216;
        size_t rowb = ((size_t)n * LL + kt * 128 + r8) * 3072 + h * 64 + c8 * 8;
        #pragma unroll
        for (int i = 0; i < 4; i++) {
            cpa16(base + (ko + (r8 + i * 32) * 72 + c8 * 8) * 2,
                  qkv + rowb + (size_t)i * 32 * 3072 + 1024);
            cpa16(base + (vo + (r8 + i * 32) * 72 + c8 * 8) * 2,
                  qkv + rowb + (size_t)i * 32 * 3072 + 2048);
        }
    };
    prefetchKV(0, 0);
    CP_COMMIT();

    float O[8][4];
    #pragma unroll
    for (int nj = 0; nj < 8; nj++)
        #pragma unroll
        for (int q = 0; q < 4; q++) O[nj][q] = 0.f;
    float l0 = 0.f, l1 = 0.f;
    unsigned aQ[4][4];
    bool qLoaded = false;

    size_t mrow = (size_t)nh * LL + (size_t)qt * 128 + w * 16;
    const unsigned* pm0 = pm + (mrow + g)     * (LL / 32);
    const unsigned* pm1 = pm + (mrow + g + 8) * (LL / 32);
    int klrow = lane & 7, ktile = lane >> 3;
    int vkv = ((lane >> 3) & 1) * 8 + (lane & 7);
    int vd  = (lane >> 4) * 8;
    int sh0 = 2 * tg;

    for (int kt = 0; kt < 16; kt++) {
        int s = kt & 1;
        if (kt + 1 < 16) { prefetchKV(kt + 1, s ^ 1); CP_COMMIT(); CP_WAIT1(); }
        else             { CP_WAIT0(); }
        __syncthreads();
        // issue packed-mask loads early; latency hides under QK MMAs
        uint4 m0 = *reinterpret_cast<const uint4*>(pm0 + kt * 4);
        uint4 m1 = *reinterpret_cast<const uint4*>(pm1 + kt * 4);
        if (!qLoaded) {
            qLoaded = true;
            #pragma unroll
            for (int tt = 0; tt < 4; tt++) {
                const __half* qp = smh + (w * 16 + g) * 72 + tt * 16 + 2 * tg;
                aQ[tt][0] = *reinterpret_cast<const unsigned*>(qp);
                aQ[tt][1] = *reinterpret_cast<const unsigned*>(qp + 8 * 72);
                aQ[tt][2] = *reinterpret_cast<const unsigned*>(qp + 8);
                aQ[tt][3] = *reinterpret_cast<const unsigned*>(qp + 8 * 72 + 8);
            }
        }
        uint32_t ko = 9216 + s * 18432, vo = ko + 9216;

        // S = Q K^T
        float sc[16][4];
        #pragma unroll
        for (int j = 0; j < 16; j++) {
            unsigned bq[2][4];
            uint32_t ka = base + ((j * 8 + klrow) * 72 + ktile * 8 + ko) * 2;
            ldsm_x4(bq[0], ka);
            ldsm_x4(bq[1], ka + 64);
            sc[j][0] = sc[j][1] = sc[j][2] = sc[j][3] = 0.f;
            #pragma unroll
            for (int tt = 0; tt < 4; tt++)
                mma_f16(sc[j], aQ[tt], bq[tt >> 1][(tt & 1) * 2], bq[tt >> 1][(tt & 1) * 2 + 1]);
        }

        // mask (bits) + exp + row sums
        #pragma unroll
        for (int j = 0; j < 16; j++) {
            unsigned w0 = (&m0.x)[j >> 2];
            unsigned w1 = (&m1.x)[j >> 2];
            int sh = (j & 3) * 8 + sh0;
            sc[j][0] = (w0 >> sh) & 1       ? 0.f : __expf(sc[j][0]);
            sc[j][1] = (w0 >> (sh + 1)) & 1 ? 0.f : __expf(sc[j][1]);
            sc[j][2] = (w1 >> sh) & 1       ? 0.f : __expf(sc[j][2]);
            sc[j][3] = (w1 >> (sh + 1)) & 1 ? 0.f : __expf(sc[j][3]);
            l0 += sc[j][0] + sc[j][1];
            l1 += sc[j][2] + sc[j][3];
        }

        // O += P @ V
        #pragma unroll
        for (int tt = 0; tt < 8; tt++) {
            unsigned pa[4];
            pa[0] = pack_f16(sc[2*tt    ][0], sc[2*tt    ][1]);
            pa[1] = pack_f16(sc[2*tt    ][2], sc[2*tt    ][3]);
            pa[2] = pack_f16(sc[2*tt + 1][0], sc[2*tt + 1][1]);
            pa[3] = pack_f16(sc[2*tt + 1][2], sc[2*tt + 1][3]);
            uint32_t va = base + ((tt * 16 + vkv) * 72 + vd + vo) * 2;
            #pragma unroll
            for (int njp = 0; njp < 4; njp++) {
                unsigned bv[4];
                ldsm_x4_t(bv, va + njp * 32);
                mma_f16(O[2*njp    ], pa, bv[0], bv[1]);
                mma_f16(O[2*njp + 1], pa, bv[2], bv[3]);
            }
        }
        __syncthreads();
    }

    l0 += __shfl_xor_sync(0xFFFFFFFFu, l0, 1);
    l0 += __shfl_xor_sync(0xFFFFFFFFu, l0, 2);
    l1 += __shfl_xor_sync(0xFFFFFFFFu, l1, 1);
    l1 += __shfl_xor_sync(0xFFFFFFFFu, l1, 2);
    float r0 = 1.f / l0, r1 = 1.f / l1;
    size_t orow = qrow0 + w * 16 + g;
    #pragma unroll
    for (int nj = 0; nj < 8; nj++) {
        int col = h * 64 + nj * 8 + 2 * tg;
        *reinterpret_cast<unsigned*>(g_attnh + orow * EN + col) =
            pack_f16(O[nj][0] * r0, O[nj][1] * r0);
        *reinterpret_cast<unsigned*>(g_attnh + (orow + 8) * EN + col) =
            pack_f16(O[nj][2] * r1, O[nj][3] * r1);
    }
}

// ---------------- launch -----------------------------------------------------
extern "C" void kernel_launch(void* const* d_in, const int* in_sizes, int n_in,
                              void* d_out, int out_size) {
    const float* x     = (const float*)d_in[0];
    const uint4* mask4 = (const uint4*)d_in[1];
    const float* ln1_s = (const float*)d_in[2];
    const float* ln1_b = (const float*)d_in[3];
    const float* Wqkv  = (const float*)d_in[4];
    const float* bqkv  = (const float*)d_in[5];
    const float* Wo    = (const float*)d_in[6];
    const float* bo    = (const float*)d_in[7];
    const float* ln2_s = (const float*)d_in[8];
    const float* ln2_b = (const float*)d_in[9];
    const float* lnf_s = (const float*)d_in[10];
    const float* lnf_b = (const float*)d_in[11];
    const float* W1    = (const float*)d_in[12];
    const float* b1    = (const float*)d_in[13];
    const float* W2    = (const float*)d_in[14];
    const float* b2    = (const float*)d_in[15];
    float* out = (float*)d_out;

    __half *p_hh, *p_qkvh, *p_attnh, *p_h2, *p_ff, *p_Wqkvt, *p_Wot, *p_W1t, *p_W2t;
    float *p_x1, *p_bqkv;
    unsigned* p_pmask;
    cudaGetSymbolAddress((void**)&p_hh,    g_hh);
    cudaGetSymbolAddress((void**)&p_qkvh,  g_qkvh);
    cudaGetSymbolAddress((void**)&p_attnh, g_attnh);
    cudaGetSymbolAddress((void**)&p_x1,    g_x1);
    cudaGetSymbolAddress((void**)&p_h2,    g_h2);
    cudaGetSymbolAddress((void**)&p_ff,    g_ff);
    cudaGetSymbolAddress((void**)&p_bqkv,  g_bqkv);
    cudaGetSymbolAddress((void**)&p_pmask, g_pmask);
    cudaGetSymbolAddress((void**)&p_Wqkvt, g_Wqkvt);
    cudaGetSymbolAddress((void**)&p_Wot,   g_Wot);
    cudaGetSymbolAddress((void**)&p_W1t,   g_W1t);
    cudaGetSymbolAddress((void**)&p_W2t,   g_W2t);

    cudaFuncSetAttribute(gemm4_k<EPI_BIAS, __half>, cudaFuncAttributeMaxDynamicSharedMemorySize, GEMM_SMEM);
    cudaFuncSetAttribute(gemm4_k<EPI_RES,  float>,  cudaFuncAttributeMaxDynamicSharedMemorySize, GEMM_SMEM);
    cudaFuncSetAttribute(gemm4_k<EPI_GELU, __half>, cudaFuncAttributeMaxDynamicSharedMemorySize, GEMM_SMEM);
    cudaFuncSetAttribute(attn_k, cudaFuncAttributeMaxDynamicSharedMemorySize, ATTN_SMEM);

    // one-time stream/event handles (host resources only; work is identical
    // every call)
    static cudaStream_t s2 = nullptr;
    static cudaEvent_t evF = nullptr, evJ = nullptr;
    if (!s2) {
        cudaStreamCreateWithFlags(&s2, cudaStreamNonBlocking);
        cudaEventCreateWithFlags(&evF, cudaEventDisableTiming);
        cudaEventCreateWithFlags(&evJ, cudaEventDisableTiming);
    }

    // fork: mask bit-pack runs on s2, overlapping transT/LN1/QKV GEMM
    cudaEventRecord(evF, 0);
    cudaStreamWaitEvent(s2, evF, 0);
    maskpack_k<<<PMW / 256, 256, 0, s2>>>(mask4, p_pmask);
    cudaEventRecord(evJ, s2);

    dim3 tb(256);
    transT_f16_k<<<dim3(3*EN/64, EN/64), tb>>>(Wqkv, p_Wqkvt, EN, 3*EN, EN, 0.125f);
    transT_f16_k<<<dim3(EN/64,   EN/64), tb>>>(Wo,   p_Wot,   EN, EN,   0, 1.f);
    transT_f16_k<<<dim3(DFFN/64, EN/64), tb>>>(W1,   p_W1t,   EN, DFFN, 0, 1.f);
    transT_f16_k<<<dim3(EN/64, DFFN/64), tb>>>(W2,   p_W2t,   DFFN, EN, 0, 1.f);
    scale_bias_k<<<3*EN/256, 256>>>(bqkv, p_bqkv);

    // 1. h = LN1(x) -> fp16
    ln1_k<<<ROWS, 256>>>(x, ln1_s, ln1_b, p_hh);
    // 2. qkv = h @ Wqkv + bqkv (fp16 out; q pre-scaled)
    gemm4_k<EPI_BIAS, __half><<<dim3(3*EN/128, ROWS/128), 128, GEMM_SMEM>>>(
        ROWS, 3*EN, EN, p_hh, p_Wqkvt, p_bqkv, nullptr, p_qkvh);

    // join: packed mask must be ready before attention
    cudaStreamWaitEvent(0, evJ, 0);
    // 3. attention
    attn_k<<<dim3(LL/128, NB*HHH), 256, ATTN_SMEM>>>(p_pmask, p_qkvh);
    // 4. x1 = x + attn @ Wo + bo
    gemm4_k<EPI_RES, float><<<dim3(EN/128, ROWS/128), 128, GEMM_SMEM>>>(
        ROWS, EN, EN, p_attnh, p_Wot, bo, x, p_x1);
    // 5. h2 = LNf(LN2(x1)) -> fp16
    ln2f_k<<<ROWS, 256>>>(p_x1, ln2_s, ln2_b, lnf_s, lnf_b, p_h2);
    // 6. ff = gelu(h2 @ W1 + b1)
    gemm4_k<EPI_GELU, __half><<<dim3(DFFN/128, ROWS/128), 128, GEMM_SMEM>>>(
        ROWS, DFFN, EN, p_h2, p_W1t, b1, nullptr, p_ff);
    // 7. out = x1 + ff @ W2 + b2
    gemm4_k<EPI_RES, float><<<dim3(EN/128, ROWS/128), 128, GEMM_SMEM>>>(
        ROWS, EN, DFFN, p_ff, p_W2t, b2, p_x1, out);
}